// round 1
// baseline (speedup 1.0000x reference)
#include <cuda_runtime.h>
#include <math.h>

#define NN 25000
#define NE 200000

// ---- scratch (no allocs allowed) ----
__device__ float g_a[NN * 32];    // per-node [a_s(8), a_v(8x3)]
__device__ float g_exp[NE];       // per-edge exp(logit)
__device__ float g_z[NN];         // segment sum of exp
__device__ float g_cnt[NN];       // segment edge count

static __device__ __forceinline__ float fsilu(float x) {
    return __fdividef(x, 1.f + __expf(-x));
}

// constants
#define INV_SQRT8  0.3535533905932738f
#define DOT_SC     0.5773502691896258f   // 1/sqrt(3)
#define CROSS_SC   0.7071067811865476f   // 1/sqrt(2)
#define OUTS_SC    0.25f                 // 1/sqrt(2*MUL)=1/4
#define OUTV_SC    0.2041241452319315f   // 1/sqrt(3*MUL)
#define LOGIT_VSC  0.5773502691896258f   // 1/sqrt(3)
#define LOGIT_SC   0.25f                 // 1/sqrt(2*MUL)

__global__ void zero_kernel(float* __restrict__ out) {
    int i = blockIdx.x * blockDim.x + threadIdx.x;
    if (i < NN * 32) out[i] = 0.f;
    if (i < NN) { g_z[i] = 0.f; g_cnt[i] = 0.f; }
}

// Per-node: a_s[n] = sum_k Wd0[k,n] qs[k],  a_v[n,c] = sum_k Wd1[k,n] qv[k,c]
__global__ void node_prep(const float* __restrict__ na,
                          const float* __restrict__ Wq0, const float* __restrict__ Wq1,
                          const float* __restrict__ Wd0, const float* __restrict__ Wd1) {
    int i = blockIdx.x * blockDim.x + threadIdx.x;
    if (i >= NN) return;
    float ns[8], nv[8][3];
#pragma unroll
    for (int m = 0; m < 8; m++) ns[m] = na[i * 32 + m];
#pragma unroll
    for (int m = 0; m < 8; m++)
#pragma unroll
        for (int c = 0; c < 3; c++) nv[m][c] = na[i * 32 + 8 + m * 3 + c];

    float qs[8], qv[8][3];
#pragma unroll
    for (int k = 0; k < 8; k++) {
        float a = 0.f;
#pragma unroll
        for (int m = 0; m < 8; m++) a += ns[m] * Wq0[m * 8 + k];
        qs[k] = a * INV_SQRT8;
    }
#pragma unroll
    for (int k = 0; k < 8; k++)
#pragma unroll
        for (int c = 0; c < 3; c++) {
            float a = 0.f;
#pragma unroll
            for (int m = 0; m < 8; m++) a += nv[m][c] * Wq1[m * 8 + k];
            qv[k][c] = a * INV_SQRT8;
        }
#pragma unroll
    for (int n = 0; n < 8; n++) {
        float a = 0.f;
#pragma unroll
        for (int k = 0; k < 8; k++) a += Wd0[k * 8 + n] * qs[k];
        g_a[i * 32 + n] = a;
    }
#pragma unroll
    for (int n = 0; n < 8; n++)
#pragma unroll
        for (int c = 0; c < 3; c++) {
            float a = 0.f;
#pragma unroll
            for (int k = 0; k < 8; k++) a += Wd1[k * 8 + n] * qv[k][c];
            g_a[i * 32 + 8 + n * 3 + c] = a;
        }
}

// w[t] (t = m*8+n, 64 values for one path) = sum_j h[j] * W2[j, p*64 + t]
__device__ __forceinline__ void compute_w(const float* __restrict__ sW2p,
                                          const float4* __restrict__ h4,
                                          float* __restrict__ w) {
#pragma unroll
    for (int t = 0; t < 64; t++) w[t] = 0.f;
#pragma unroll 1
    for (int j4 = 0; j4 < 16; j4++) {
        float4 hh = h4[j4];
        const float* b0 = sW2p + (j4 * 4 + 0) * 320;
        const float* b1 = sW2p + (j4 * 4 + 1) * 320;
        const float* b2 = sW2p + (j4 * 4 + 2) * 320;
        const float* b3 = sW2p + (j4 * 4 + 3) * 320;
#pragma unroll
        for (int t4 = 0; t4 < 16; t4++) {
            float4 a = *(const float4*)(b0 + t4 * 4);
            float4 b = *(const float4*)(b1 + t4 * 4);
            float4 c = *(const float4*)(b2 + t4 * 4);
            float4 d = *(const float4*)(b3 + t4 * 4);
            w[t4 * 4 + 0] += hh.x * a.x + hh.y * b.x + hh.z * c.x + hh.w * d.x;
            w[t4 * 4 + 1] += hh.x * a.y + hh.y * b.y + hh.z * c.y + hh.w * d.y;
            w[t4 * 4 + 2] += hh.x * a.z + hh.y * b.z + hh.z * c.z + hh.w * d.z;
            w[t4 * 4 + 3] += hh.x * a.w + hh.y * b.w + hh.z * c.w + hh.w * d.w;
        }
    }
}

// IS_K = 1: key pass (logits, exp, z/cnt atomics). IS_K = 0: value pass (output atomics).
template <int IS_K>
__global__ void __launch_bounds__(128) edge_pass(
    const float* __restrict__ na, const int* __restrict__ ei,
    const float* __restrict__ eattr, const float* __restrict__ esh,
    const float* __restrict__ W1, const float* __restrict__ W2,
    float* __restrict__ out) {
    extern __shared__ float smem[];
    float* sW2 = smem;           // 64*320
    float* sW1 = smem + 20480;   // 16*64
    {
        const float4* g2 = (const float4*)W2;
        float4* d2 = (float4*)sW2;
        for (int t = threadIdx.x; t < 5120; t += blockDim.x) d2[t] = g2[t];
        const float4* g1 = (const float4*)W1;
        float4* d1 = (float4*)sW1;
        for (int t = threadIdx.x; t < 256; t += blockDim.x) d1[t] = g1[t];
    }
    __syncthreads();

    int e = blockIdx.x * blockDim.x + threadIdx.x;
    if (e >= NE) return;

    // edge attr -> registers
    float ea[16];
    {
        const float4* p = (const float4*)(eattr + e * 16);
#pragma unroll
        for (int q = 0; q < 4; q++) {
            float4 v = p[q];
            ea[q * 4 + 0] = v.x; ea[q * 4 + 1] = v.y;
            ea[q * 4 + 2] = v.z; ea[q * 4 + 3] = v.w;
        }
    }

    // radial hidden layer: h[j] = silu((ea . W1[:,j]) * 0.25) * 0.125 (folds /sqrt(64))
    float4 h4[16];
#pragma unroll 1
    for (int j4 = 0; j4 < 16; j4++) {
        float acc[4];
#pragma unroll
        for (int jj = 0; jj < 4; jj++) {
            float a = 0.f;
            int j = j4 * 4 + jj;
#pragma unroll
            for (int i = 0; i < 16; i++) a += ea[i] * sW1[i * 64 + j];
            acc[jj] = fsilu(a * 0.25f) * 0.125f;
        }
        h4[j4] = make_float4(acc[0], acc[1], acc[2], acc[3]);
    }

    int src = ei[e];
    int dst = ei[NE + e];

    float xs[8], xv[8][3];
#pragma unroll
    for (int m = 0; m < 8; m++) xs[m] = na[src * 32 + m];
#pragma unroll
    for (int m = 0; m < 8; m++)
#pragma unroll
        for (int c = 0; c < 3; c++) xv[m][c] = na[src * 32 + 8 + m * 3 + c];

    float4 sh = *(const float4*)(esh + e * 4);
    float s0 = sh.x, s1x = sh.y, s1y = sh.z, s1z = sh.w;

    float os[8], ov[8][3];
    float w[64];

    // path 0: out_s += (w0 @ xs) * s0
    compute_w(sW2, h4, w);
#pragma unroll
    for (int n = 0; n < 8; n++) {
        float t = 0.f;
#pragma unroll
        for (int m = 0; m < 8; m++) t += w[m * 8 + n] * xs[m];
        os[n] = t * s0;
    }
    // path 1: out_v += (w1 @ xs) outer s1
    compute_w(sW2 + 64, h4, w);
#pragma unroll
    for (int n = 0; n < 8; n++) {
        float t = 0.f;
#pragma unroll
        for (int m = 0; m < 8; m++) t += w[m * 8 + n] * xs[m];
        ov[n][0] = t * s1x; ov[n][1] = t * s1y; ov[n][2] = t * s1z;
    }
    // path 2: out_v += (w2 @ xv) * s0
    compute_w(sW2 + 128, h4, w);
#pragma unroll
    for (int n = 0; n < 8; n++)
#pragma unroll
        for (int c = 0; c < 3; c++) {
            float t = 0.f;
#pragma unroll
            for (int m = 0; m < 8; m++) t += w[m * 8 + n] * xv[m][c];
            ov[n][c] += t * s0;
        }
    // path 3: out_s += w3 @ dot, dot[m] = (xv[m].s1)/sqrt3
    compute_w(sW2 + 192, h4, w);
    {
        float dm[8];
#pragma unroll
        for (int m = 0; m < 8; m++)
            dm[m] = (xv[m][0] * s1x + xv[m][1] * s1y + xv[m][2] * s1z) * DOT_SC;
#pragma unroll
        for (int n = 0; n < 8; n++) {
            float t = 0.f;
#pragma unroll
            for (int m = 0; m < 8; m++) t += w[m * 8 + n] * dm[m];
            os[n] += t;
        }
    }
    // path 4: out_v += w4 @ cross, cross[m] = (xv[m] x s1)/sqrt2
    compute_w(sW2 + 256, h4, w);
#pragma unroll
    for (int m = 0; m < 8; m++) {
        float c0 = (xv[m][1] * s1z - xv[m][2] * s1y) * CROSS_SC;
        float c1 = (xv[m][2] * s1x - xv[m][0] * s1z) * CROSS_SC;
        float c2 = (xv[m][0] * s1y - xv[m][1] * s1x) * CROSS_SC;
#pragma unroll
        for (int n = 0; n < 8; n++) {
            float wv = w[m * 8 + n];
            ov[n][0] += wv * c0; ov[n][1] += wv * c1; ov[n][2] += wv * c2;
        }
    }

    if (IS_K) {
        // logit = (a_s . ks + (a_v . kv)/sqrt3) / sqrt(2*MUL)
        const float* ad = g_a + dst * 32;
        float ls = 0.f, lv = 0.f;
#pragma unroll
        for (int n = 0; n < 8; n++) ls += ad[n] * (os[n] * OUTS_SC);
#pragma unroll
        for (int n = 0; n < 8; n++)
#pragma unroll
            for (int c = 0; c < 3; c++)
                lv += ad[8 + n * 3 + c] * (ov[n][c] * OUTV_SC);
        float logit = (ls + lv * LOGIT_VSC) * LOGIT_SC;
        float ex = __expf(logit);
        g_exp[e] = ex;
        atomicAdd(&g_z[dst], ex);
        atomicAdd(&g_cnt[dst], 1.0f);
    } else {
        // out[dst] += sqrt(exp_e) * v_edge (normalization by sqrt(z) in finalize)
        float att = sqrtf(g_exp[e]);
        float* ob = out + dst * 32;
#pragma unroll
        for (int n = 0; n < 8; n++)
            atomicAdd(&ob[n], att * (os[n] * OUTS_SC));
#pragma unroll
        for (int n = 0; n < 8; n++)
#pragma unroll
            for (int c = 0; c < 3; c++)
                atomicAdd(&ob[8 + n * 3 + c], att * (ov[n][c] * OUTV_SC));
    }
}

__global__ void finalize(float* __restrict__ out) {
    int i = blockIdx.x * blockDim.x + threadIdx.x;
    if (i >= NN) return;
    float c = g_cnt[i];
    float z = g_z[i] / fmaxf(c, 1.0f);
    float s = (z > 0.f) ? rsqrtf(z) : 0.f;
#pragma unroll
    for (int t = 0; t < 32; t++) out[i * 32 + t] *= s;
}

#define EDGE_SMEM ((20480 + 1024) * sizeof(float))

extern "C" void kernel_launch(void* const* d_in, const int* in_sizes, int n_in,
                              void* d_out, int out_size) {
    const float* na    = (const float*)d_in[0];
    const int*   ei    = (const int*)d_in[1];
    const float* eattr = (const float*)d_in[2];
    const float* esh   = (const float*)d_in[3];
    const float* Wq0   = (const float*)d_in[4];
    const float* Wq1   = (const float*)d_in[5];
    const float* kW1   = (const float*)d_in[6];
    const float* kW2   = (const float*)d_in[7];
    const float* vW1   = (const float*)d_in[8];
    const float* vW2   = (const float*)d_in[9];
    const float* Wd0   = (const float*)d_in[10];
    const float* Wd1   = (const float*)d_in[11];
    float* out = (float*)d_out;

    cudaFuncSetAttribute(edge_pass<1>, cudaFuncAttributeMaxDynamicSharedMemorySize, (int)EDGE_SMEM);
    cudaFuncSetAttribute(edge_pass<0>, cudaFuncAttributeMaxDynamicSharedMemorySize, (int)EDGE_SMEM);

    zero_kernel<<<(NN * 32 + 255) / 256, 256>>>(out);
    node_prep<<<(NN + 127) / 128, 128>>>(na, Wq0, Wq1, Wd0, Wd1);
    int eblocks = (NE + 127) / 128;
    edge_pass<1><<<eblocks, 128, EDGE_SMEM>>>(na, ei, eattr, esh, kW1, kW2, out);
    edge_pass<0><<<eblocks, 128, EDGE_SMEM>>>(na, ei, eattr, esh, vW1, vW2, out);
    finalize<<<(NN + 127) / 128, 128>>>(out);
}

// round 4
// speedup vs baseline: 3.9717x; 3.9717x over previous
#include <cuda_runtime.h>
#include <math.h>
#include <stdint.h>

#define NN 25000
#define NE 200000
#define NTILES ((NE + 255) / 256)
#define FULLMASK 0xffffffffu

// ---- scratch (no allocs allowed) ----
__device__ float g_a[NN * 32];    // per-node [a_s(8), a_v(8x3)]
__device__ float g_exp[NE];       // per-edge exp(logit)
__device__ float g_zc[NN * 2];    // interleaved [z, cnt]

#define INV_SQRT8  0.3535533905932738f
#define DOT_SC     0.5773502691896258f   // 1/sqrt(3)
#define CROSS_SC   0.7071067811865476f   // 1/sqrt(2)
#define OUTS_SC    0.25f                 // 1/sqrt(2*MUL)
#define OUTV_SC    0.2041241452319315f   // 1/sqrt(3*MUL)
#define LOGIT_VSC  0.5773502691896258f   // 1/sqrt(3)
#define LOGIT_SC   0.25f                 // 1/sqrt(2*MUL)

static __device__ __forceinline__ float fsilu(float x) {
    return __fdividef(x, 1.f + __expf(-x));
}

__device__ __forceinline__ uint32_t tf32r(float x) {
    uint32_t v;
    asm("cvt.rna.tf32.f32 %0, %1;" : "=r"(v) : "f"(x));
    return v;
}

__device__ __forceinline__ void mma8(float* d, const uint32_t* a, const uint32_t* b) {
    asm volatile("mma.sync.aligned.m16n8k8.row.col.f32.tf32.tf32.f32 "
        "{%0,%1,%2,%3}, {%4,%5,%6,%7}, {%8,%9}, {%0,%1,%2,%3};"
        : "+f"(d[0]), "+f"(d[1]), "+f"(d[2]), "+f"(d[3])
        : "r"(a[0]), "r"(a[1]), "r"(a[2]), "r"(a[3]), "r"(b[0]), "r"(b[1]));
}

__device__ __forceinline__ void red2(float* p, float a, float b) {
    asm volatile("red.global.add.v2.f32 [%0], {%1, %2};"
        :: "l"(p), "f"(a), "f"(b) : "memory");
}

// =====================  small kernels  =====================
__global__ void zero_kernel(float* __restrict__ out) {
    int i = blockIdx.x * blockDim.x + threadIdx.x;
    if (i < NN * 32) out[i] = 0.f;
    if (i < NN * 2) g_zc[i] = 0.f;
}

__global__ void node_prep(const float* __restrict__ na,
                          const float* __restrict__ Wq0, const float* __restrict__ Wq1,
                          const float* __restrict__ Wd0, const float* __restrict__ Wd1) {
    int i = blockIdx.x * blockDim.x + threadIdx.x;
    if (i >= NN) return;
    float ns[8], nv[8][3];
#pragma unroll
    for (int m = 0; m < 8; m++) ns[m] = na[i * 32 + m];
#pragma unroll
    for (int m = 0; m < 8; m++)
#pragma unroll
        for (int c = 0; c < 3; c++) nv[m][c] = na[i * 32 + 8 + m * 3 + c];
    float qs[8], qv[8][3];
#pragma unroll
    for (int k = 0; k < 8; k++) {
        float a = 0.f;
#pragma unroll
        for (int m = 0; m < 8; m++) a += ns[m] * Wq0[m * 8 + k];
        qs[k] = a * INV_SQRT8;
    }
#pragma unroll
    for (int k = 0; k < 8; k++)
#pragma unroll
        for (int c = 0; c < 3; c++) {
            float a = 0.f;
#pragma unroll
            for (int m = 0; m < 8; m++) a += nv[m][c] * Wq1[m * 8 + k];
            qv[k][c] = a * INV_SQRT8;
        }
#pragma unroll
    for (int n = 0; n < 8; n++) {
        float a = 0.f;
#pragma unroll
        for (int k = 0; k < 8; k++) a += Wd0[k * 8 + n] * qs[k];
        g_a[i * 32 + n] = a;
    }
#pragma unroll
    for (int n = 0; n < 8; n++)
#pragma unroll
        for (int c = 0; c < 3; c++) {
            float a = 0.f;
#pragma unroll
            for (int k = 0; k < 8; k++) a += Wd1[k * 8 + n] * qv[k][c];
            g_a[i * 32 + 8 + n * 3 + c] = a;
        }
}

__global__ void finalize(float* __restrict__ out) {
    int i = blockIdx.x * blockDim.x + threadIdx.x;
    if (i >= NN) return;
    float c = g_zc[i * 2 + 1];
    float z = g_zc[i * 2] / fmaxf(c, 1.0f);
    float s = (z > 0.f) ? rsqrtf(z) : 0.f;
#pragma unroll
    for (int t = 0; t < 32; t++) out[i * 32 + t] *= s;
}

// =====================  fused edge pass (mma.sync tf32)  =====================
// smem (floats): sW1[1024] | sH[256*68] | sB[320*68]
#define SH_OFF 1024
#define SB_OFF (1024 + 256 * 68)
#define SMEM_FLOATS (1024 + 256 * 68 + 320 * 68)
#define SMEM_BYTES (SMEM_FLOATS * 4)

// GEMM for one path: D[2][8][4] (m16 tiles x n8 tiles x frag), K=64
#define GEMM_PATH(P, D) do {                                                     \
    _Pragma("unroll")                                                            \
    for (int mt_ = 0; mt_ < 2; mt_++)                                            \
        _Pragma("unroll")                                                        \
        for (int nt_ = 0; nt_ < 8; nt_++)                                        \
            _Pragma("unroll")                                                    \
            for (int q_ = 0; q_ < 4; q_++) D[mt_][nt_][q_] = 0.f;                \
    _Pragma("unroll 2")                                                          \
    for (int k0 = 0; k0 < 64; k0 += 8) {                                         \
        uint32_t a0_[4], a1_[4], bb_[8][2];                                      \
        const int ar_ = (wid * 32 + r4) * 68 + k0 + qc;                          \
        a0_[0] = sHu[ar_];            a0_[1] = sHu[ar_ + 8 * 68];                \
        a0_[2] = sHu[ar_ + 4];        a0_[3] = sHu[ar_ + 8 * 68 + 4];            \
        a1_[0] = sHu[ar_ + 16 * 68];  a1_[1] = sHu[ar_ + 24 * 68];               \
        a1_[2] = sHu[ar_ + 16 * 68 + 4]; a1_[3] = sHu[ar_ + 24 * 68 + 4];        \
        const int br_ = ((P) * 64 + r4) * 68 + k0 + qc;                          \
        _Pragma("unroll")                                                        \
        for (int nt_ = 0; nt_ < 8; nt_++) {                                      \
            bb_[nt_][0] = sBu[br_ + nt_ * 8 * 68];                               \
            bb_[nt_][1] = sBu[br_ + nt_ * 8 * 68 + 4];                           \
        }                                                                        \
        _Pragma("unroll")                                                        \
        for (int nt_ = 0; nt_ < 8; nt_++) {                                      \
            mma8(D[0][nt_], a0_, bb_[nt_]);                                      \
            mma8(D[1][nt_], a1_, bb_[nt_]);                                      \
        }                                                                        \
    } } while (0)

// scalar-path epilogue: T[mt][half][pair] += D * f(m) shuffled from row owner
#define EPI_ACC(D, FEXPR, T) do {                                                \
    _Pragma("unroll")                                                            \
    for (int mt_ = 0; mt_ < 2; mt_++) {                                          \
        _Pragma("unroll")                                                        \
        for (int m = 0; m < 8; m++) {                                            \
            float fv_ = (FEXPR);                                                 \
            float f0_ = __shfl_sync(FULLMASK, fv_, mt_ * 16 + r4);               \
            float f1_ = __shfl_sync(FULLMASK, fv_, mt_ * 16 + 8 + r4);           \
            T[mt_][0][0] += D[mt_][m][0] * f0_;                                  \
            T[mt_][0][1] += D[mt_][m][1] * f0_;                                  \
            T[mt_][1][0] += D[mt_][m][2] * f1_;                                  \
            T[mt_][1][1] += D[mt_][m][3] * f1_;                                  \
        }                                                                        \
    } } while (0)

// vector-path epilogue: ovA[mt][half][pair][c] += D * f_c(m)
#define EPI_VEC(D, FX, FY, FZ) do {                                              \
    _Pragma("unroll")                                                            \
    for (int mt_ = 0; mt_ < 2; mt_++) {                                          \
        _Pragma("unroll")                                                        \
        for (int m = 0; m < 8; m++) {                                            \
            float fx_ = (FX), fy_ = (FY), fz_ = (FZ);                            \
            float gx0_ = __shfl_sync(FULLMASK, fx_, mt_ * 16 + r4);              \
            float gx1_ = __shfl_sync(FULLMASK, fx_, mt_ * 16 + 8 + r4);          \
            float gy0_ = __shfl_sync(FULLMASK, fy_, mt_ * 16 + r4);              \
            float gy1_ = __shfl_sync(FULLMASK, fy_, mt_ * 16 + 8 + r4);          \
            float gz0_ = __shfl_sync(FULLMASK, fz_, mt_ * 16 + r4);              \
            float gz1_ = __shfl_sync(FULLMASK, fz_, mt_ * 16 + 8 + r4);          \
            ovA[mt_][0][0][0] += D[mt_][m][0] * gx0_;                            \
            ovA[mt_][0][1][0] += D[mt_][m][1] * gx0_;                            \
            ovA[mt_][1][0][0] += D[mt_][m][2] * gx1_;                            \
            ovA[mt_][1][1][0] += D[mt_][m][3] * gx1_;                            \
            ovA[mt_][0][0][1] += D[mt_][m][0] * gy0_;                            \
            ovA[mt_][0][1][1] += D[mt_][m][1] * gy0_;                            \
            ovA[mt_][1][0][1] += D[mt_][m][2] * gy1_;                            \
            ovA[mt_][1][1][1] += D[mt_][m][3] * gy1_;                            \
            ovA[mt_][0][0][2] += D[mt_][m][0] * gz0_;                            \
            ovA[mt_][0][1][2] += D[mt_][m][1] * gz0_;                            \
            ovA[mt_][1][0][2] += D[mt_][m][2] * gz1_;                            \
            ovA[mt_][1][1][2] += D[mt_][m][3] * gz1_;                            \
        }                                                                        \
    } } while (0)

template <int IS_K>
__global__ void __launch_bounds__(256, 1) fused_pass(
    const float* __restrict__ na, const int* __restrict__ ei,
    const float* __restrict__ eattr, const float* __restrict__ esh,
    const float* __restrict__ W1, const float* __restrict__ W2,
    float* __restrict__ out) {
    extern __shared__ float sm[];
    float* sW1 = sm;
    uint32_t* sHu = (uint32_t*)(sm + SH_OFF);
    uint32_t* sBu = (uint32_t*)(sm + SB_OFF);

    const int tid = threadIdx.x;
    const int wid = tid >> 5;
    const int lane = tid & 31;
    const int r4 = lane >> 2;
    const int qc = lane & 3;

    // stage W1 (fp32) and W2^T (tf32, stride 68 -> conflict-free frag loads)
    for (int idx = tid; idx < 1024; idx += 256) sW1[idx] = W1[idx];
    for (int idx = tid; idx < 20480; idx += 256) {
        int j = idx / 320;
        int t = idx - j * 320;
        sBu[t * 68 + j] = tf32r(W2[idx]);
    }
    __syncthreads();

    const float4* sW1v = (const float4*)sW1;

    for (int tile = blockIdx.x; tile < NTILES; tile += gridDim.x) {
        const int e = tile * 256 + tid;
        const bool valid = (e < NE);

        // ---- radial hidden layer: acc[j] = ea . W1[:,j] ----
        float ea[16];
        if (valid) {
            const float4* p = (const float4*)(eattr + (size_t)e * 16);
#pragma unroll
            for (int q = 0; q < 4; q++) {
                float4 v = p[q];
                ea[q * 4 + 0] = v.x; ea[q * 4 + 1] = v.y;
                ea[q * 4 + 2] = v.z; ea[q * 4 + 3] = v.w;
            }
        } else {
#pragma unroll
            for (int q = 0; q < 16; q++) ea[q] = 0.f;
        }
        float acc[64];
#pragma unroll
        for (int j = 0; j < 64; j++) acc[j] = 0.f;
#pragma unroll
        for (int i = 0; i < 16; i++) {
            float a = ea[i];
#pragma unroll
            for (int j4 = 0; j4 < 16; j4++) {
                float4 wv = sW1v[i * 16 + j4];
                acc[j4 * 4 + 0] += a * wv.x;
                acc[j4 * 4 + 1] += a * wv.y;
                acc[j4 * 4 + 2] += a * wv.z;
                acc[j4 * 4 + 3] += a * wv.w;
            }
        }

        __syncthreads();   // prior tile's H readers done
        // silu + tf32-round + store A row (16B-aligned, stride 68 floats)
#pragma unroll
        for (int j4 = 0; j4 < 16; j4++) {
            uint4 v;
            v.x = tf32r(fsilu(acc[j4 * 4 + 0] * 0.25f) * 0.125f);
            v.y = tf32r(fsilu(acc[j4 * 4 + 1] * 0.25f) * 0.125f);
            v.z = tf32r(fsilu(acc[j4 * 4 + 2] * 0.25f) * 0.125f);
            v.w = tf32r(fsilu(acc[j4 * 4 + 3] * 0.25f) * 0.125f);
            *(uint4*)(sHu + tid * 68 + j4 * 4) = v;
        }
        __syncthreads();

        // ---- per-edge features (owner = this thread's edge) ----
        int dst = 0;
        float xs[8], xv[8][3];
        float s0 = 0.f, s1x = 0.f, s1y = 0.f, s1z = 0.f;
        float m0 = 0.f, m1 = 0.f;   // scalar / vector feature scales
        if (valid) {
            int srcn = ei[e];
            dst = ei[NE + e];
            const float4* xp = (const float4*)(na + (size_t)srcn * 32);
#pragma unroll
            for (int q = 0; q < 2; q++) {
                float4 v = xp[q];
                xs[q * 4 + 0] = v.x; xs[q * 4 + 1] = v.y;
                xs[q * 4 + 2] = v.z; xs[q * 4 + 3] = v.w;
            }
#pragma unroll
            for (int q = 0; q < 6; q++) {
                float4 v = xp[2 + q];
                ((float*)xv)[q * 4 + 0] = v.x; ((float*)xv)[q * 4 + 1] = v.y;
                ((float*)xv)[q * 4 + 2] = v.z; ((float*)xv)[q * 4 + 3] = v.w;
            }
            float4 sh = *(const float4*)(esh + (size_t)e * 4);
            s0 = sh.x; s1x = sh.y; s1y = sh.z; s1z = sh.w;
            if (IS_K) {
                m0 = OUTS_SC * LOGIT_SC;
                m1 = OUTV_SC * LOGIT_VSC * LOGIT_SC;
            } else {
                float att = sqrtf(g_exp[e]);
                m0 = att * OUTS_SC;
                m1 = att * OUTV_SC;
            }
        } else {
#pragma unroll
            for (int m = 0; m < 8; m++) {
                xs[m] = 0.f; xv[m][0] = xv[m][1] = xv[m][2] = 0.f;
            }
        }
        const float s0A = s0 * m0;           // path0
        const float dA  = DOT_SC * m0;       // path3
        const float s0B = s0 * m1;           // path2
        const float cB  = CROSS_SC * m1;     // path4

        float d[2][8][4];
        float osA[2][2][2];
        float ovA[2][2][2][3];
#pragma unroll
        for (int a = 0; a < 2; a++)
#pragma unroll
            for (int b = 0; b < 2; b++) {
                osA[a][b][0] = osA[a][b][1] = 0.f;
#pragma unroll
                for (int p = 0; p < 2; p++)
                    ovA[a][b][p][0] = ovA[a][b][p][1] = ovA[a][b][p][2] = 0.f;
            }

        // path 0: os += w0 @ (xs*s0)
        GEMM_PATH(0, d);
        EPI_ACC(d, xs[m] * s0A, osA);

        // path 1: ov += (w1 @ xs) outer s1
        GEMM_PATH(1, d);
        {
            float t8a[2][2][2];
#pragma unroll
            for (int a = 0; a < 2; a++)
#pragma unroll
                for (int b = 0; b < 2; b++) t8a[a][b][0] = t8a[a][b][1] = 0.f;
            EPI_ACC(d, xs[m] * m1, t8a);
#pragma unroll
            for (int mt = 0; mt < 2; mt++)
#pragma unroll
                for (int h = 0; h < 2; h++) {
                    int srcl = mt * 16 + h * 8 + r4;
                    float sx = __shfl_sync(FULLMASK, s1x, srcl);
                    float sy = __shfl_sync(FULLMASK, s1y, srcl);
                    float sz = __shfl_sync(FULLMASK, s1z, srcl);
                    ovA[mt][h][0][0] += t8a[mt][h][0] * sx;
                    ovA[mt][h][1][0] += t8a[mt][h][1] * sx;
                    ovA[mt][h][0][1] += t8a[mt][h][0] * sy;
                    ovA[mt][h][1][1] += t8a[mt][h][1] * sy;
                    ovA[mt][h][0][2] += t8a[mt][h][0] * sz;
                    ovA[mt][h][1][2] += t8a[mt][h][1] * sz;
                }
        }

        // path 2: ov += (w2 @ xv) * s0
        GEMM_PATH(2, d);
        EPI_VEC(d, xv[m][0] * s0B, xv[m][1] * s0B, xv[m][2] * s0B);

        // path 3: os += w3 @ ((xv.s1)/sqrt3)
        GEMM_PATH(3, d);
        EPI_ACC(d, (xv[m][0] * s1x + xv[m][1] * s1y + xv[m][2] * s1z) * dA, osA);

        // path 4: ov += w4 @ (cross(xv, s1)/sqrt2)
        GEMM_PATH(4, d);
        EPI_VEC(d, (xv[m][1] * s1z - xv[m][2] * s1y) * cB,
                   (xv[m][2] * s1x - xv[m][0] * s1z) * cB,
                   (xv[m][0] * s1y - xv[m][1] * s1x) * cB);

        // ---- emission (lane owns cols n=2qc, 2qc+1 of its 4 rows) ----
#pragma unroll
        for (int mt = 0; mt < 2; mt++)
#pragma unroll
            for (int h = 0; h < 2; h++) {
                int srcl = mt * 16 + h * 8 + r4;
                int dstr = __shfl_sync(FULLMASK, dst, srcl);
                if (IS_K) {
                    const float* ap = g_a + (size_t)dstr * 32;
                    float2 a01 = *(const float2*)(ap + 2 * qc);
                    float lp = a01.x * osA[mt][h][0] + a01.y * osA[mt][h][1];
                    float2 v0 = *(const float2*)(ap + 8 + 6 * qc);
                    float2 v1 = *(const float2*)(ap + 8 + 6 * qc + 2);
                    float2 v2 = *(const float2*)(ap + 8 + 6 * qc + 4);
                    lp += v0.x * ovA[mt][h][0][0] + v0.y * ovA[mt][h][0][1];
                    lp += v1.x * ovA[mt][h][0][2] + v1.y * ovA[mt][h][1][0];
                    lp += v2.x * ovA[mt][h][1][1] + v2.y * ovA[mt][h][1][2];
                    lp += __shfl_xor_sync(FULLMASK, lp, 1);
                    lp += __shfl_xor_sync(FULLMASK, lp, 2);
                    if (qc == 0) {
                        int er = tile * 256 + wid * 32 + srcl;
                        if (er < NE) {
                            float ex = __expf(lp);
                            g_exp[er] = ex;
                            red2(&g_zc[(size_t)dstr * 2], ex, 1.0f);
                        }
                    }
                } else {
                    float* ob = out + (size_t)dstr * 32;
                    red2(ob + 2 * qc, osA[mt][h][0], osA[mt][h][1]);
                    red2(ob + 8 + 6 * qc,     ovA[mt][h][0][0], ovA[mt][h][0][1]);
                    red2(ob + 8 + 6 * qc + 2, ovA[mt][h][0][2], ovA[mt][h][1][0]);
                    red2(ob + 8 + 6 * qc + 4, ovA[mt][h][1][1], ovA[mt][h][1][2]);
                }
            }
    }
}

extern "C" void kernel_launch(void* const* d_in, const int* in_sizes, int n_in,
                              void* d_out, int out_size) {
    const float* na    = (const float*)d_in[0];
    const int*   ei    = (const int*)d_in[1];
    const float* eattr = (const float*)d_in[2];
    const float* esh   = (const float*)d_in[3];
    const float* Wq0   = (const float*)d_in[4];
    const float* Wq1   = (const float*)d_in[5];
    const float* kW1   = (const float*)d_in[6];
    const float* kW2   = (const float*)d_in[7];
    const float* vW1   = (const float*)d_in[8];
    const float* vW2   = (const float*)d_in[9];
    const float* Wd0   = (const float*)d_in[10];
    const float* Wd1   = (const float*)d_in[11];
    float* out = (float*)d_out;

    cudaFuncSetAttribute(fused_pass<1>, cudaFuncAttributeMaxDynamicSharedMemorySize, SMEM_BYTES);
    cudaFuncSetAttribute(fused_pass<0>, cudaFuncAttributeMaxDynamicSharedMemorySize, SMEM_BYTES);

    zero_kernel<<<(NN * 32 + 255) / 256, 256>>>(out);
    node_prep<<<(NN + 127) / 128, 128>>>(na, Wq0, Wq1, Wd0, Wd1);
    fused_pass<1><<<148, 256, SMEM_BYTES>>>(na, ei, eattr, esh, kW1, kW2, out);
    fused_pass<0><<<148, 256, SMEM_BYTES>>>(na, ei, eattr, esh, vW1, vW2, out);
    finalize<<<(NN + 127) / 128, 128>>>(out);
}

// round 6
// speedup vs baseline: 4.0886x; 1.0294x over previous
#include <cuda_runtime.h>
#include <math.h>
#include <stdint.h>

#define NN 25000
#define NE 200000
#define NTILES ((NE + 255) / 256)
#define FULLMASK 0xffffffffu

// ---- scratch (no allocs allowed) ----
__device__ float g_a[NN * 32];    // per-node [a_s(8), a_v(8x3)]
__device__ float g_exp[NE];       // per-edge exp(logit)
__device__ float g_zc[NN * 2];    // interleaved [z, cnt]

#define INV_SQRT8  0.3535533905932738f
#define DOT_SC     0.5773502691896258f   // 1/sqrt(3)
#define CROSS_SC   0.7071067811865476f   // 1/sqrt(2)
#define OUTS_SC    0.25f                 // 1/sqrt(2*MUL)
#define OUTV_SC    0.2041241452319315f   // 1/sqrt(3*MUL)
#define LOGIT_VSC  0.5773502691896258f   // 1/sqrt(3)
#define LOGIT_SC   0.25f                 // 1/sqrt(2*MUL)

static __device__ __forceinline__ float fsilu(float x) {
    return __fdividef(x, 1.f + __expf(-x));
}

__device__ __forceinline__ uint32_t tf32r(float x) {
    uint32_t v;
    asm("cvt.rna.tf32.f32 %0, %1;" : "=r"(v) : "f"(x));
    return v;
}

__device__ __forceinline__ void mma8(float* d, const uint32_t* a, const uint32_t* b) {
    asm volatile("mma.sync.aligned.m16n8k8.row.col.f32.tf32.tf32.f32 "
        "{%0,%1,%2,%3}, {%4,%5,%6,%7}, {%8,%9}, {%0,%1,%2,%3};"
        : "+f"(d[0]), "+f"(d[1]), "+f"(d[2]), "+f"(d[3])
        : "r"(a[0]), "r"(a[1]), "r"(a[2]), "r"(a[3]), "r"(b[0]), "r"(b[1]));
}

__device__ __forceinline__ void red2(float* p, float a, float b) {
    asm volatile("red.global.add.v2.f32 [%0], {%1, %2};"
        :: "l"(p), "f"(a), "f"(b) : "memory");
}

// =====================  small kernels  =====================
__global__ void zero_kernel(float* __restrict__ out) {
    int i = blockIdx.x * blockDim.x + threadIdx.x;
    if (i < NN * 32) out[i] = 0.f;
    if (i < NN * 2) g_zc[i] = 0.f;
}

__global__ void node_prep(const float* __restrict__ na,
                          const float* __restrict__ Wq0, const float* __restrict__ Wq1,
                          const float* __restrict__ Wd0, const float* __restrict__ Wd1) {
    int i = blockIdx.x * blockDim.x + threadIdx.x;
    if (i >= NN) return;
    float ns[8], nv[8][3];
#pragma unroll
    for (int m = 0; m < 8; m++) ns[m] = na[i * 32 + m];
#pragma unroll
    for (int m = 0; m < 8; m++)
#pragma unroll
        for (int c = 0; c < 3; c++) nv[m][c] = na[i * 32 + 8 + m * 3 + c];
    float qs[8], qv[8][3];
#pragma unroll
    for (int k = 0; k < 8; k++) {
        float a = 0.f;
#pragma unroll
        for (int m = 0; m < 8; m++) a += ns[m] * Wq0[m * 8 + k];
        qs[k] = a * INV_SQRT8;
    }
#pragma unroll
    for (int k = 0; k < 8; k++)
#pragma unroll
        for (int c = 0; c < 3; c++) {
            float a = 0.f;
#pragma unroll
            for (int m = 0; m < 8; m++) a += nv[m][c] * Wq1[m * 8 + k];
            qv[k][c] = a * INV_SQRT8;
        }
#pragma unroll
    for (int n = 0; n < 8; n++) {
        float a = 0.f;
#pragma unroll
        for (int k = 0; k < 8; k++) a += Wd0[k * 8 + n] * qs[k];
        g_a[i * 32 + n] = a;
    }
#pragma unroll
    for (int n = 0; n < 8; n++)
#pragma unroll
        for (int c = 0; c < 3; c++) {
            float a = 0.f;
#pragma unroll
            for (int k = 0; k < 8; k++) a += Wd1[k * 8 + n] * qv[k][c];
            g_a[i * 32 + 8 + n * 3 + c] = a;
        }
}

__global__ void finalize(float* __restrict__ out) {
    int i = blockIdx.x * blockDim.x + threadIdx.x;
    if (i >= NN) return;
    float c = g_zc[i * 2 + 1];
    float z = g_zc[i * 2] / fmaxf(c, 1.0f);
    float s = (z > 0.f) ? rsqrtf(z) : 0.f;
#pragma unroll
    for (int t = 0; t < 32; t++) out[i * 32 + t] *= s;
}

// =====================  fused edge pass (mma.sync tf32)  =====================
// smem (floats): sW1[1024] | sH[256*68] | sBf4[5120 float4 = 20480 floats]
#define SH_OFF 1024
#define SB_OFF (1024 + 256 * 68)
#define SMEM_FLOATS (1024 + 256 * 68 + 20480)
#define SMEM_BYTES (SMEM_FLOATS * 4)

// GEMM of one n-tile (m-index of the tensor product): dnt[2][4], K=64
#define GEMM_NT(P, NT, DNT) do {                                                 \
    _Pragma("unroll")                                                            \
    for (int q_ = 0; q_ < 4; q_++) { DNT[0][q_] = 0.f; DNT[1][q_] = 0.f; }       \
    _Pragma("unroll")                                                            \
    for (int kp_ = 0; kp_ < 4; kp_++) {                                          \
        float4 bv_ = sBf4[(((P) * 8 + (NT)) * 4 + kp_) * 32 + lane];             \
        uint32_t b01_[2] = {__float_as_uint(bv_.x), __float_as_uint(bv_.y)};     \
        uint32_t b23_[2] = {__float_as_uint(bv_.z), __float_as_uint(bv_.w)};     \
        mma8(DNT[0], &aF[2 * kp_][0], b01_);                                     \
        mma8(DNT[1], &aF[2 * kp_][4], b01_);                                     \
        mma8(DNT[0], &aF[2 * kp_ + 1][0], b23_);                                 \
        mma8(DNT[1], &aF[2 * kp_ + 1][4], b23_);                                 \
    } } while (0)

// scalar path: T[mt][h][pair] += dnt * f(m) shuffled from the row-owner lane
#define PATH_S(P, FEXPR, T) do {                                                 \
    _Pragma("unroll")                                                            \
    for (int nt_ = 0; nt_ < 8; nt_++) {                                          \
        float dnt[2][4];                                                         \
        GEMM_NT(P, nt_, dnt);                                                    \
        { int m = nt_; float fv_ = (FEXPR);                                      \
          float f00_ = __shfl_sync(FULLMASK, fv_, r4);                           \
          float f01_ = __shfl_sync(FULLMASK, fv_, 8 + r4);                       \
          float f10_ = __shfl_sync(FULLMASK, fv_, 16 + r4);                      \
          float f11_ = __shfl_sync(FULLMASK, fv_, 24 + r4);                      \
          T[0][0][0] += dnt[0][0] * f00_; T[0][0][1] += dnt[0][1] * f00_;        \
          T[0][1][0] += dnt[0][2] * f01_; T[0][1][1] += dnt[0][3] * f01_;        \
          T[1][0][0] += dnt[1][0] * f10_; T[1][0][1] += dnt[1][1] * f10_;        \
          T[1][1][0] += dnt[1][2] * f11_; T[1][1][1] += dnt[1][3] * f11_; }      \
    } } while (0)

// vector path: ovA[mt][h][pair][c] += dnt * f_c(m)
#define PATH_V(P, FX, FY, FZ) do {                                               \
    _Pragma("unroll")                                                            \
    for (int nt_ = 0; nt_ < 8; nt_++) {                                          \
        float dnt[2][4];                                                         \
        GEMM_NT(P, nt_, dnt);                                                    \
        { int m = nt_;                                                           \
          float fx_ = (FX), fy_ = (FY), fz_ = (FZ);                              \
          float gx00_ = __shfl_sync(FULLMASK, fx_, r4);                          \
          float gx01_ = __shfl_sync(FULLMASK, fx_, 8 + r4);                      \
          float gx10_ = __shfl_sync(FULLMASK, fx_, 16 + r4);                     \
          float gx11_ = __shfl_sync(FULLMASK, fx_, 24 + r4);                     \
          float gy00_ = __shfl_sync(FULLMASK, fy_, r4);                          \
          float gy01_ = __shfl_sync(FULLMASK, fy_, 8 + r4);                      \
          float gy10_ = __shfl_sync(FULLMASK, fy_, 16 + r4);                     \
          float gy11_ = __shfl_sync(FULLMASK, fy_, 24 + r4);                     \
          float gz00_ = __shfl_sync(FULLMASK, fz_, r4);                          \
          float gz01_ = __shfl_sync(FULLMASK, fz_, 8 + r4);                      \
          float gz10_ = __shfl_sync(FULLMASK, fz_, 16 + r4);                     \
          float gz11_ = __shfl_sync(FULLMASK, fz_, 24 + r4);                     \
          ovA[0][0][0][0] += dnt[0][0] * gx00_; ovA[0][0][1][0] += dnt[0][1] * gx00_; \
          ovA[0][1][0][0] += dnt[0][2] * gx01_; ovA[0][1][1][0] += dnt[0][3] * gx01_; \
          ovA[1][0][0][0] += dnt[1][0] * gx10_; ovA[1][0][1][0] += dnt[1][1] * gx10_; \
          ovA[1][1][0][0] += dnt[1][2] * gx11_; ovA[1][1][1][0] += dnt[1][3] * gx11_; \
          ovA[0][0][0][1] += dnt[0][0] * gy00_; ovA[0][0][1][1] += dnt[0][1] * gy00_; \
          ovA[0][1][0][1] += dnt[0][2] * gy01_; ovA[0][1][1][1] += dnt[0][3] * gy01_; \
          ovA[1][0][0][1] += dnt[1][0] * gy10_; ovA[1][0][1][1] += dnt[1][1] * gy10_; \
          ovA[1][1][0][1] += dnt[1][2] * gy11_; ovA[1][1][1][1] += dnt[1][3] * gy11_; \
          ovA[0][0][0][2] += dnt[0][0] * gz00_; ovA[0][0][1][2] += dnt[0][1] * gz00_; \
          ovA[0][1][0][2] += dnt[0][2] * gz01_; ovA[0][1][1][2] += dnt[0][3] * gz01_; \
          ovA[1][0][0][2] += dnt[1][0] * gz10_; ovA[1][0][1][2] += dnt[1][1] * gz10_; \
          ovA[1][1][0][2] += dnt[1][2] * gz11_; ovA[1][1][1][2] += dnt[1][3] * gz11_; } \
    } } while (0)

template <int IS_K>
__global__ void __launch_bounds__(256, 1) fused_pass(
    const float* __restrict__ na, const int* __restrict__ ei,
    const float* __restrict__ eattr, const float* __restrict__ esh,
    const float* __restrict__ W1, const float* __restrict__ W2,
    float* __restrict__ out) {
    extern __shared__ float sm[];
    float* sW1 = sm;
    uint32_t* sHu = (uint32_t*)(sm + SH_OFF);
    const float4* sBf4 = (const float4*)(sm + SB_OFF);

    const int tid = threadIdx.x;
    const int wid = tid >> 5;
    const int lane = tid & 31;
    const int r4 = lane >> 2;
    const int qc = lane & 3;

    // stage W1 (fp32) and W2 in mma-fragment-major order (tf32):
    // slot = (ntg*4 + kp)*32 + lane; float4 = b-frags of k-steps 2kp, 2kp+1
    for (int idx = tid; idx < 1024; idx += 256) sW1[idx] = W1[idx];
    {
        float4* wB = (float4*)(sm + SB_OFF);
        for (int idx = tid; idx < 5120; idx += 256) {
            int lane_ = idx & 31;
            int kp = (idx >> 5) & 3;
            int ntg = idx >> 7;
            int n = ntg * 8 + (lane_ >> 2);
            int q = lane_ & 3;
            int k0 = kp * 16;
            float4 v;
            v.x = __uint_as_float(tf32r(W2[(k0 + q) * 320 + n]));
            v.y = __uint_as_float(tf32r(W2[(k0 + 4 + q) * 320 + n]));
            v.z = __uint_as_float(tf32r(W2[(k0 + 8 + q) * 320 + n]));
            v.w = __uint_as_float(tf32r(W2[(k0 + 12 + q) * 320 + n]));
            wB[idx] = v;
        }
    }
    __syncthreads();

    const float4* sW1v = (const float4*)sW1;

    for (int tile = blockIdx.x; tile < NTILES; tile += gridDim.x) {
        const int e = tile * 256 + tid;
        const bool valid = (e < NE);

        // ---- radial hidden layer: acc[j] = ea . W1[:,j] ----
        float ea[16];
        if (valid) {
            const float4* p = (const float4*)(eattr + (size_t)e * 16);
#pragma unroll
            for (int q = 0; q < 4; q++) {
                float4 v = p[q];
                ea[q * 4 + 0] = v.x; ea[q * 4 + 1] = v.y;
                ea[q * 4 + 2] = v.z; ea[q * 4 + 3] = v.w;
            }
        } else {
#pragma unroll
            for (int q = 0; q < 16; q++) ea[q] = 0.f;
        }
        float acc[64];
#pragma unroll
        for (int j = 0; j < 64; j++) acc[j] = 0.f;
#pragma unroll
        for (int i = 0; i < 16; i++) {
            float a = ea[i];
#pragma unroll
            for (int j4 = 0; j4 < 16; j4++) {
                float4 wv = sW1v[i * 16 + j4];
                acc[j4 * 4 + 0] += a * wv.x;
                acc[j4 * 4 + 1] += a * wv.y;
                acc[j4 * 4 + 2] += a * wv.z;
                acc[j4 * 4 + 3] += a * wv.w;
            }
        }

        __syncthreads();   // prior tile's H readers done
        // silu + tf32-round + store A row (16B-aligned, stride 68 floats)
#pragma unroll
        for (int j4 = 0; j4 < 16; j4++) {
            uint4 v;
            v.x = tf32r(fsilu(acc[j4 * 4 + 0] * 0.25f) * 0.125f);
            v.y = tf32r(fsilu(acc[j4 * 4 + 1] * 0.25f) * 0.125f);
            v.z = tf32r(fsilu(acc[j4 * 4 + 2] * 0.25f) * 0.125f);
            v.w = tf32r(fsilu(acc[j4 * 4 + 3] * 0.25f) * 0.125f);
            *(uint4*)(sHu + tid * 68 + j4 * 4) = v;
        }
        __syncthreads();

        // ---- per-edge features (owner = this thread's edge) ----
        int dst = 0;
        float xs[8], xv[8][3];
        float s0 = 0.f, s1x = 0.f, s1y = 0.f, s1z = 0.f;
        float m0 = 0.f, m1 = 0.f;
        if (valid) {
            int srcn = ei[e];
            dst = ei[NE + e];
            const float4* xp = (const float4*)(na + (size_t)srcn * 32);
#pragma unroll
            for (int q = 0; q < 2; q++) {
                float4 v = xp[q];
                xs[q * 4 + 0] = v.x; xs[q * 4 + 1] = v.y;
                xs[q * 4 + 2] = v.z; xs[q * 4 + 3] = v.w;
            }
#pragma unroll
            for (int q = 0; q < 6; q++) {
                float4 v = xp[2 + q];
                ((float*)xv)[q * 4 + 0] = v.x; ((float*)xv)[q * 4 + 1] = v.y;
                ((float*)xv)[q * 4 + 2] = v.z; ((float*)xv)[q * 4 + 3] = v.w;
            }
            float4 sh = *(const float4*)(esh + (size_t)e * 4);
            s0 = sh.x; s1x = sh.y; s1y = sh.z; s1z = sh.w;
            if (IS_K) {
                m0 = OUTS_SC * LOGIT_SC;
                m1 = OUTV_SC * LOGIT_VSC * LOGIT_SC;
            } else {
                float att = sqrtf(g_exp[e]);
                m0 = att * OUTS_SC;
                m1 = att * OUTV_SC;
            }
        } else {
#pragma unroll
            for (int m = 0; m < 8; m++) {
                xs[m] = 0.f; xv[m][0] = xv[m][1] = xv[m][2] = 0.f;
            }
        }
        const float s0A = s0 * m0;           // path0
        const float dA  = DOT_SC * m0;       // path3
        const float s0B = s0 * m1;           // path2
        const float cB  = CROSS_SC * m1;     // path4

        // ---- hoisted A fragments (shared across all 5 paths) ----
        uint32_t aF[8][8];
#pragma unroll
        for (int kk = 0; kk < 8; kk++) {
            const int ar = (wid * 32 + r4) * 68 + kk * 8 + qc;
            aF[kk][0] = sHu[ar];                aF[kk][1] = sHu[ar + 8 * 68];
            aF[kk][2] = sHu[ar + 4];            aF[kk][3] = sHu[ar + 8 * 68 + 4];
            aF[kk][4] = sHu[ar + 16 * 68];      aF[kk][5] = sHu[ar + 24 * 68];
            aF[kk][6] = sHu[ar + 16 * 68 + 4];  aF[kk][7] = sHu[ar + 24 * 68 + 4];
        }

        float osA[2][2][2];
        float ovA[2][2][2][3];
#pragma unroll
        for (int a = 0; a < 2; a++)
#pragma unroll
            for (int b = 0; b < 2; b++) {
                osA[a][b][0] = osA[a][b][1] = 0.f;
#pragma unroll
                for (int p = 0; p < 2; p++)
                    ovA[a][b][p][0] = ovA[a][b][p][1] = ovA[a][b][p][2] = 0.f;
            }

        // path 0: os += w0 @ (xs*s0)
        PATH_S(0, xs[m] * s0A, osA);

        // path 1: ov += (w1 @ xs) outer s1
        {
            float t8a[2][2][2];
#pragma unroll
            for (int a = 0; a < 2; a++)
#pragma unroll
                for (int b = 0; b < 2; b++) t8a[a][b][0] = t8a[a][b][1] = 0.f;
            PATH_S(1, xs[m] * m1, t8a);
#pragma unroll
            for (int mt = 0; mt < 2; mt++)
#pragma unroll
                for (int h = 0; h < 2; h++) {
                    int srcl = mt * 16 + h * 8 + r4;
                    float sx = __shfl_sync(FULLMASK, s1x, srcl);
                    float sy = __shfl_sync(FULLMASK, s1y, srcl);
                    float sz = __shfl_sync(FULLMASK, s1z, srcl);
                    ovA[mt][h][0][0] += t8a[mt][h][0] * sx;
                    ovA[mt][h][1][0] += t8a[mt][h][1] * sx;
                    ovA[mt][h][0][1] += t8a[mt][h][0] * sy;
                    ovA[mt][h][1][1] += t8a[mt][h][1] * sy;
                    ovA[mt][h][0][2] += t8a[mt][h][0] * sz;
                    ovA[mt][h][1][2] += t8a[mt][h][1] * sz;
                }
        }

        // path 2: ov += (w2 @ xv) * s0
        PATH_V(2, xv[m][0] * s0B, xv[m][1] * s0B, xv[m][2] * s0B);

        // path 3: os += w3 @ ((xv.s1)/sqrt3)
        PATH_S(3, (xv[m][0] * s1x + xv[m][1] * s1y + xv[m][2] * s1z) * dA, osA);

        // path 4: ov += w4 @ (cross(xv, s1)/sqrt2)
        PATH_V(4, (xv[m][1] * s1z - xv[m][2] * s1y) * cB,
                  (xv[m][2] * s1x - xv[m][0] * s1z) * cB,
                  (xv[m][0] * s1y - xv[m][1] * s1x) * cB);

        // ---- emission (lane owns cols n=2qc, 2qc+1 of its 4 rows) ----
#pragma unroll
        for (int mt = 0; mt < 2; mt++)
#pragma unroll
            for (int h = 0; h < 2; h++) {
                int srcl = mt * 16 + h * 8 + r4;
                int dstr = __shfl_sync(FULLMASK, dst, srcl);
                if (IS_K) {
                    const float* ap = g_a + (size_t)dstr * 32;
                    float2 a01 = *(const float2*)(ap + 2 * qc);
                    float lp = a01.x * osA[mt][h][0] + a01.y * osA[mt][h][1];
                    float2 v0 = *(const float2*)(ap + 8 + 6 * qc);
                    float2 v1 = *(const float2*)(ap + 8 + 6 * qc + 2);
                    float2 v2 = *(const float2*)(ap + 8 + 6 * qc + 4);
                    lp += v0.x * ovA[mt][h][0][0] + v0.y * ovA[mt][h][0][1];
                    lp += v1.x * ovA[mt][h][0][2] + v1.y * ovA[mt][h][1][0];
                    lp += v2.x * ovA[mt][h][1][1] + v2.y * ovA[mt][h][1][2];
                    lp += __shfl_xor_sync(FULLMASK, lp, 1);
                    lp += __shfl_xor_sync(FULLMASK, lp, 2);
                    if (qc == 0) {
                        int er = tile * 256 + wid * 32 + srcl;
                        if (er < NE) {
                            float ex = __expf(lp);
                            g_exp[er] = ex;
                            red2(&g_zc[(size_t)dstr * 2], ex, 1.0f);
                        }
                    }
                } else {
                    float* ob = out + (size_t)dstr * 32;
                    red2(ob + 2 * qc, osA[mt][h][0], osA[mt][h][1]);
                    red2(ob + 8 + 6 * qc,     ovA[mt][h][0][0], ovA[mt][h][0][1]);
                    red2(ob + 8 + 6 * qc + 2, ovA[mt][h][0][2], ovA[mt][h][1][0]);
                    red2(ob + 8 + 6 * qc + 4, ovA[mt][h][1][1], ovA[mt][h][1][2]);
                }
            }
    }
}

extern "C" void kernel_launch(void* const* d_in, const int* in_sizes, int n_in,
                              void* d_out, int out_size) {
    const float* na    = (const float*)d_in[0];
    const int*   ei    = (const int*)d_in[1];
    const float* eattr = (const float*)d_in[2];
    const float* esh   = (const float*)d_in[3];
    const float* Wq0   = (const float*)d_in[4];
    const float* Wq1   = (const float*)d_in[5];
    const float* kW1   = (const float*)d_in[6];
    const float* kW2   = (const float*)d_in[7];
    const float* vW1   = (const float*)d_in[8];
    const float* vW2   = (const float*)d_in[9];
    const float* Wd0   = (const float*)d_in[10];
    const float* Wd1   = (const float*)d_in[11];
    float* out = (float*)d_out;

    cudaFuncSetAttribute(fused_pass<1>, cudaFuncAttributeMaxDynamicSharedMemorySize, SMEM_BYTES);
    cudaFuncSetAttribute(fused_pass<0>, cudaFuncAttributeMaxDynamicSharedMemorySize, SMEM_BYTES);

    zero_kernel<<<(NN * 32 + 255) / 256, 256>>>(out);
    node_prep<<<(NN + 127) / 128, 128>>>(na, Wq0, Wq1, Wd0, Wd1);
    fused_pass<1><<<148, 256, SMEM_BYTES>>>(na, ei, eattr, esh, kW1, kW2, out);
    fused_pass<0><<<148, 256, SMEM_BYTES>>>(na, ei, eattr, esh, vW1, vW2, out);
    finalize<<<(NN + 127) / 128, 128>>>(out);
}

// round 7
// speedup vs baseline: 5.5959x; 1.3687x over previous
#include <cuda_runtime.h>
#include <cuda_fp16.h>
#include <math.h>
#include <stdint.h>

#define NN 25000
#define NE 200000
#define NTILES ((NE + 255) / 256)
#define FULLMASK 0xffffffffu

// ---- scratch (no allocs allowed) ----
__device__ float g_a[NN * 32];    // per-node [a_s(8), a_v(8x3)]
__device__ float g_exp[NE];       // per-edge exp(logit)
__device__ float g_zc[NN * 2];    // interleaved [z, cnt]

#define INV_SQRT8  0.3535533905932738f
#define DOT_SC     0.5773502691896258f   // 1/sqrt(3)
#define CROSS_SC   0.7071067811865476f   // 1/sqrt(2)
#define OUTS_SC    0.25f                 // 1/sqrt(2*MUL)
#define OUTV_SC    0.2041241452319315f   // 1/sqrt(3*MUL)
#define LOGIT_VSC  0.5773502691896258f   // 1/sqrt(3)
#define LOGIT_SC   0.25f                 // 1/sqrt(2*MUL)

static __device__ __forceinline__ float fsilu(float x) {
    return __fdividef(x, 1.f + __expf(-x));
}

__device__ __forceinline__ uint32_t pkh2(float a, float b) {
    __half2 h = __floats2half2_rn(a, b);   // lo = a (smaller k index)
    return *(uint32_t*)&h;
}

__device__ __forceinline__ void mma16(float* d, const uint32_t* a, uint32_t b0, uint32_t b1) {
    asm volatile("mma.sync.aligned.m16n8k16.row.col.f32.f16.f16.f32 "
        "{%0,%1,%2,%3}, {%4,%5,%6,%7}, {%8,%9}, {%0,%1,%2,%3};"
        : "+f"(d[0]), "+f"(d[1]), "+f"(d[2]), "+f"(d[3])
        : "r"(a[0]), "r"(a[1]), "r"(a[2]), "r"(a[3]), "r"(b0), "r"(b1));
}

__device__ __forceinline__ void red2(float* p, float a, float b) {
    asm volatile("red.global.add.v2.f32 [%0], {%1, %2};"
        :: "l"(p), "f"(a), "f"(b) : "memory");
}

// =====================  small kernels  =====================
__global__ void zero_kernel(float* __restrict__ out) {
    int i = blockIdx.x * blockDim.x + threadIdx.x;
    if (i < NN * 32) out[i] = 0.f;
    if (i < NN * 2) g_zc[i] = 0.f;
}

__global__ void node_prep(const float* __restrict__ na,
                          const float* __restrict__ Wq0, const float* __restrict__ Wq1,
                          const float* __restrict__ Wd0, const float* __restrict__ Wd1) {
    int i = blockIdx.x * blockDim.x + threadIdx.x;
    if (i >= NN) return;
    float ns[8], nv[8][3];
#pragma unroll
    for (int m = 0; m < 8; m++) ns[m] = na[i * 32 + m];
#pragma unroll
    for (int m = 0; m < 8; m++)
#pragma unroll
        for (int c = 0; c < 3; c++) nv[m][c] = na[i * 32 + 8 + m * 3 + c];
    float qs[8], qv[8][3];
#pragma unroll
    for (int k = 0; k < 8; k++) {
        float a = 0.f;
#pragma unroll
        for (int m = 0; m < 8; m++) a += ns[m] * Wq0[m * 8 + k];
        qs[k] = a * INV_SQRT8;
    }
#pragma unroll
    for (int k = 0; k < 8; k++)
#pragma unroll
        for (int c = 0; c < 3; c++) {
            float a = 0.f;
#pragma unroll
            for (int m = 0; m < 8; m++) a += nv[m][c] * Wq1[m * 8 + k];
            qv[k][c] = a * INV_SQRT8;
        }
#pragma unroll
    for (int n = 0; n < 8; n++) {
        float a = 0.f;
#pragma unroll
        for (int k = 0; k < 8; k++) a += Wd0[k * 8 + n] * qs[k];
        g_a[i * 32 + n] = a;
    }
#pragma unroll
    for (int n = 0; n < 8; n++)
#pragma unroll
        for (int c = 0; c < 3; c++) {
            float a = 0.f;
#pragma unroll
            for (int k = 0; k < 8; k++) a += Wd1[k * 8 + n] * qv[k][c];
            g_a[i * 32 + 8 + n * 3 + c] = a;
        }
}

__global__ void finalize(float* __restrict__ out) {
    int i = blockIdx.x * blockDim.x + threadIdx.x;
    if (i >= NN) return;
    float c = g_zc[i * 2 + 1];
    float z = g_zc[i * 2] / fmaxf(c, 1.0f);
    float s = (z > 0.f) ? rsqrtf(z) : 0.f;
#pragma unroll
    for (int t = 0; t < 32; t++) out[i * 32 + t] *= s;
}

// =====================  fused edge pass (mma.sync fp16)  =====================
// smem (f32 units): sW1[1024] | sHu[256*36 u32] | sB[2560 uint4 = 10240 u32]
#define ST 36                         // H row stride in u32 (half2 units)
#define SH_OFF 1024
#define SB_OFF (1024 + 256 * ST)
#define SMEM_FLOATS (SB_OFF + 10240)
#define SMEM_BYTES (SMEM_FLOATS * 4)

// GEMM of one n-tile (= m index of tensor product): dnt[2][4], K=64 (2 uint4 B loads)
#define GEMM_NT(P, NT, DNT) do {                                                 \
    _Pragma("unroll")                                                            \
    for (int q_ = 0; q_ < 4; q_++) { DNT[0][q_] = 0.f; DNT[1][q_] = 0.f; }       \
    _Pragma("unroll")                                                            \
    for (int kkp_ = 0; kkp_ < 2; kkp_++) {                                       \
        uint4 bv_ = sBf4[(((P) * 8 + (NT)) * 2 + kkp_) * 32 + lane];             \
        mma16(DNT[0], &aF[kkp_ * 2][0], bv_.x, bv_.y);                           \
        mma16(DNT[1], &aF[kkp_ * 2][4], bv_.x, bv_.y);                           \
        mma16(DNT[0], &aF[kkp_ * 2 + 1][0], bv_.z, bv_.w);                       \
        mma16(DNT[1], &aF[kkp_ * 2 + 1][4], bv_.z, bv_.w);                       \
    } } while (0)

// scalar path: T[mt][h][pair] += dnt * f(m) shuffled from the row-owner lane
#define PATH_S(P, FEXPR, T) do {                                                 \
    _Pragma("unroll")                                                            \
    for (int nt_ = 0; nt_ < 8; nt_++) {                                          \
        float dnt[2][4];                                                         \
        GEMM_NT(P, nt_, dnt);                                                    \
        { int m = nt_; float fv_ = (FEXPR);                                      \
          float f00_ = __shfl_sync(FULLMASK, fv_, r4);                           \
          float f01_ = __shfl_sync(FULLMASK, fv_, 8 + r4);                       \
          float f10_ = __shfl_sync(FULLMASK, fv_, 16 + r4);                      \
          float f11_ = __shfl_sync(FULLMASK, fv_, 24 + r4);                      \
          T[0][0][0] += dnt[0][0] * f00_; T[0][0][1] += dnt[0][1] * f00_;        \
          T[0][1][0] += dnt[0][2] * f01_; T[0][1][1] += dnt[0][3] * f01_;        \
          T[1][0][0] += dnt[1][0] * f10_; T[1][0][1] += dnt[1][1] * f10_;        \
          T[1][1][0] += dnt[1][2] * f11_; T[1][1][1] += dnt[1][3] * f11_; }      \
    } } while (0)

// vector path: ovA[mt][h][pair][c] += dnt * f_c(m)
#define PATH_V(P, FX, FY, FZ) do {                                               \
    _Pragma("unroll")                                                            \
    for (int nt_ = 0; nt_ < 8; nt_++) {                                          \
        float dnt[2][4];                                                         \
        GEMM_NT(P, nt_, dnt);                                                    \
        { int m = nt_;                                                           \
          float fx_ = (FX), fy_ = (FY), fz_ = (FZ);                              \
          float gx00_ = __shfl_sync(FULLMASK, fx_, r4);                          \
          float gx01_ = __shfl_sync(FULLMASK, fx_, 8 + r4);                      \
          float gx10_ = __shfl_sync(FULLMASK, fx_, 16 + r4);                     \
          float gx11_ = __shfl_sync(FULLMASK, fx_, 24 + r4);                     \
          float gy00_ = __shfl_sync(FULLMASK, fy_, r4);                          \
          float gy01_ = __shfl_sync(FULLMASK, fy_, 8 + r4);                      \
          float gy10_ = __shfl_sync(FULLMASK, fy_, 16 + r4);                     \
          float gy11_ = __shfl_sync(FULLMASK, fy_, 24 + r4);                     \
          float gz00_ = __shfl_sync(FULLMASK, fz_, r4);                          \
          float gz01_ = __shfl_sync(FULLMASK, fz_, 8 + r4);                      \
          float gz10_ = __shfl_sync(FULLMASK, fz_, 16 + r4);                     \
          float gz11_ = __shfl_sync(FULLMASK, fz_, 24 + r4);                     \
          ovA[0][0][0][0] += dnt[0][0] * gx00_; ovA[0][0][1][0] += dnt[0][1] * gx00_; \
          ovA[0][1][0][0] += dnt[0][2] * gx01_; ovA[0][1][1][0] += dnt[0][3] * gx01_; \
          ovA[1][0][0][0] += dnt[1][0] * gx10_; ovA[1][0][1][0] += dnt[1][1] * gx10_; \
          ovA[1][1][0][0] += dnt[1][2] * gx11_; ovA[1][1][1][0] += dnt[1][3] * gx11_; \
          ovA[0][0][0][1] += dnt[0][0] * gy00_; ovA[0][0][1][1] += dnt[0][1] * gy00_; \
          ovA[0][1][0][1] += dnt[0][2] * gy01_; ovA[0][1][1][1] += dnt[0][3] * gy01_; \
          ovA[1][0][0][1] += dnt[1][0] * gy10_; ovA[1][0][1][1] += dnt[1][1] * gy10_; \
          ovA[1][1][0][1] += dnt[1][2] * gy11_; ovA[1][1][1][1] += dnt[1][3] * gy11_; \
          ovA[0][0][0][2] += dnt[0][0] * gz00_; ovA[0][0][1][2] += dnt[0][1] * gz00_; \
          ovA[0][1][0][2] += dnt[0][2] * gz01_; ovA[0][1][1][2] += dnt[0][3] * gz01_; \
          ovA[1][0][0][2] += dnt[1][0] * gz10_; ovA[1][0][1][2] += dnt[1][1] * gz10_; \
          ovA[1][1][0][2] += dnt[1][2] * gz11_; ovA[1][1][1][2] += dnt[1][3] * gz11_; } \
    } } while (0)

template <int IS_K>
__global__ void __launch_bounds__(256, 2) fused_pass(
    const float* __restrict__ na, const int* __restrict__ ei,
    const float* __restrict__ eattr, const float* __restrict__ esh,
    const float* __restrict__ W1, const float* __restrict__ W2,
    float* __restrict__ out) {
    extern __shared__ float sm[];
    float* sW1 = sm;
    uint32_t* sHu = (uint32_t*)(sm + SH_OFF);
    const uint4* sBf4 = (const uint4*)(sm + SB_OFF);

    const int tid = threadIdx.x;
    const int wid = tid >> 5;
    const int lane = tid & 31;
    const int r4 = lane >> 2;
    const int qc = lane & 3;

    // stage W1 (fp32) and W2 as fp16 mma B-fragments:
    // uint4 idx = ((p*8+nt)*2 + kkp)*32 + lane; {b0,b1} of kstep 2kkp, then 2kkp+1
    for (int idx = tid; idx < 1024; idx += 256) sW1[idx] = W1[idx];
    {
        uint4* wB = (uint4*)(sm + SB_OFF);
        for (int idx = tid; idx < 2560; idx += 256) {
            int lane_ = idx & 31;
            int kkp = (idx >> 5) & 1;
            int nt = (idx >> 6) & 7;
            int p = idx >> 9;
            int col = p * 64 + nt * 8 + (lane_ >> 2);
            int k0 = (kkp * 2) * 16 + 2 * (lane_ & 3);
            int k1 = k0 + 16;
            uint4 v;
            v.x = pkh2(W2[k0 * 320 + col],       W2[(k0 + 1) * 320 + col]);
            v.y = pkh2(W2[(k0 + 8) * 320 + col], W2[(k0 + 9) * 320 + col]);
            v.z = pkh2(W2[k1 * 320 + col],       W2[(k1 + 1) * 320 + col]);
            v.w = pkh2(W2[(k1 + 8) * 320 + col], W2[(k1 + 9) * 320 + col]);
            wB[idx] = v;
        }
    }
    __syncthreads();

    const float4* sW1v = (const float4*)sW1;

    for (int tile = blockIdx.x; tile < NTILES; tile += gridDim.x) {
        const int e = tile * 256 + tid;
        const bool valid = (e < NE);

        // ---- radial hidden layer: acc[j] = ea . W1[:,j] ----
        float ea[16];
        if (valid) {
            const float4* p = (const float4*)(eattr + (size_t)e * 16);
#pragma unroll
            for (int q = 0; q < 4; q++) {
                float4 v = p[q];
                ea[q * 4 + 0] = v.x; ea[q * 4 + 1] = v.y;
                ea[q * 4 + 2] = v.z; ea[q * 4 + 3] = v.w;
            }
        } else {
#pragma unroll
            for (int q = 0; q < 16; q++) ea[q] = 0.f;
        }
        float acc[64];
#pragma unroll
        for (int j = 0; j < 64; j++) acc[j] = 0.f;
#pragma unroll
        for (int i = 0; i < 16; i++) {
            float a = ea[i];
#pragma unroll
            for (int j4 = 0; j4 < 16; j4++) {
                float4 wv = sW1v[i * 16 + j4];
                acc[j4 * 4 + 0] += a * wv.x;
                acc[j4 * 4 + 1] += a * wv.y;
                acc[j4 * 4 + 2] += a * wv.z;
                acc[j4 * 4 + 3] += a * wv.w;
            }
        }

        __syncthreads();   // prior tile's H readers done
        // silu + fp16 pack + store A row (8 uint4 = 64 halves, stride ST u32)
#pragma unroll
        for (int j4 = 0; j4 < 8; j4++) {
            uint4 v;
            v.x = pkh2(fsilu(acc[j4 * 8 + 0] * 0.25f) * 0.125f,
                       fsilu(acc[j4 * 8 + 1] * 0.25f) * 0.125f);
            v.y = pkh2(fsilu(acc[j4 * 8 + 2] * 0.25f) * 0.125f,
                       fsilu(acc[j4 * 8 + 3] * 0.25f) * 0.125f);
            v.z = pkh2(fsilu(acc[j4 * 8 + 4] * 0.25f) * 0.125f,
                       fsilu(acc[j4 * 8 + 5] * 0.25f) * 0.125f);
            v.w = pkh2(fsilu(acc[j4 * 8 + 6] * 0.25f) * 0.125f,
                       fsilu(acc[j4 * 8 + 7] * 0.25f) * 0.125f);
            *(uint4*)(sHu + tid * ST + j4 * 4) = v;
        }
        __syncthreads();

        // ---- per-edge features (owner = this thread's edge) ----
        int dst = 0;
        float xs[8], xv[8][3];
        float s0 = 0.f, s1x = 0.f, s1y = 0.f, s1z = 0.f;
        float m0 = 0.f, m1 = 0.f;
        if (valid) {
            int srcn = ei[e];
            dst = ei[NE + e];
            const float4* xp = (const float4*)(na + (size_t)srcn * 32);
#pragma unroll
            for (int q = 0; q < 2; q++) {
                float4 v = xp[q];
                xs[q * 4 + 0] = v.x; xs[q * 4 + 1] = v.y;
                xs[q * 4 + 2] = v.z; xs[q * 4 + 3] = v.w;
            }
#pragma unroll
            for (int q = 0; q < 6; q++) {
                float4 v = xp[2 + q];
                ((float*)xv)[q * 4 + 0] = v.x; ((float*)xv)[q * 4 + 1] = v.y;
                ((float*)xv)[q * 4 + 2] = v.z; ((float*)xv)[q * 4 + 3] = v.w;
            }
            float4 sh = *(const float4*)(esh + (size_t)e * 4);
            s0 = sh.x; s1x = sh.y; s1y = sh.z; s1z = sh.w;
            if (IS_K) {
                m0 = OUTS_SC * LOGIT_SC;
                m1 = OUTV_SC * LOGIT_VSC * LOGIT_SC;
            } else {
                float att = sqrtf(g_exp[e]);
                m0 = att * OUTS_SC;
                m1 = att * OUTV_SC;
            }
        } else {
#pragma unroll
            for (int m = 0; m < 8; m++) {
                xs[m] = 0.f; xv[m][0] = xv[m][1] = xv[m][2] = 0.f;
            }
        }
        const float s0A = s0 * m0;           // path0
        const float dA  = DOT_SC * m0;       // path3
        const float s0B = s0 * m1;           // path2
        const float cB  = CROSS_SC * m1;     // path4

        // ---- hoisted A fragments: aF[kstep][mt*4 + reg] ----
        uint32_t aF[4][8];
#pragma unroll
        for (int kk = 0; kk < 4; kk++)
#pragma unroll
            for (int mt = 0; mt < 2; mt++) {
                const int b = (wid * 32 + mt * 16 + r4) * ST + kk * 8 + qc;
                aF[kk][mt * 4 + 0] = sHu[b];
                aF[kk][mt * 4 + 1] = sHu[b + 8 * ST];
                aF[kk][mt * 4 + 2] = sHu[b + 4];
                aF[kk][mt * 4 + 3] = sHu[b + 8 * ST + 4];
            }

        float osA[2][2][2];
        float ovA[2][2][2][3];
#pragma unroll
        for (int a = 0; a < 2; a++)
#pragma unroll
            for (int b = 0; b < 2; b++) {
                osA[a][b][0] = osA[a][b][1] = 0.f;
#pragma unroll
                for (int p = 0; p < 2; p++)
                    ovA[a][b][p][0] = ovA[a][b][p][1] = ovA[a][b][p][2] = 0.f;
            }

        // path 0: os += w0 @ (xs*s0)
        PATH_S(0, xs[m] * s0A, osA);

        // path 1: ov += (w1 @ xs) outer s1
        {
            float t8a[2][2][2];
#pragma unroll
            for (int a = 0; a < 2; a++)
#pragma unroll
                for (int b = 0; b < 2; b++) t8a[a][b][0] = t8a[a][b][1] = 0.f;
            PATH_S(1, xs[m] * m1, t8a);
#pragma unroll
            for (int mt = 0; mt < 2; mt++)
#pragma unroll
                for (int h = 0; h < 2; h++) {
                    int srcl = mt * 16 + h * 8 + r4;
                    float sx = __shfl_sync(FULLMASK, s1x, srcl);
                    float sy = __shfl_sync(FULLMASK, s1y, srcl);
                    float sz = __shfl_sync(FULLMASK, s1z, srcl);
                    ovA[mt][h][0][0] += t8a[mt][h][0] * sx;
                    ovA[mt][h][1][0] += t8a[mt][h][1] * sx;
                    ovA[mt][h][0][1] += t8a[mt][h][0] * sy;
                    ovA[mt][h][1][1] += t8a[mt][h][1] * sy;
                    ovA[mt][h][0][2] += t8a[mt][h][0] * sz;
                    ovA[mt][h][1][2] += t8a[mt][h][1] * sz;
                }
        }

        // path 2: ov += (w2 @ xv) * s0
        PATH_V(2, xv[m][0] * s0B, xv[m][1] * s0B, xv[m][2] * s0B);

        // path 3: os += w3 @ ((xv.s1)/sqrt3)
        PATH_S(3, (xv[m][0] * s1x + xv[m][1] * s1y + xv[m][2] * s1z) * dA, osA);

        // path 4: ov += w4 @ (cross(xv, s1)/sqrt2)
        PATH_V(4, (xv[m][1] * s1z - xv[m][2] * s1y) * cB,
                  (xv[m][2] * s1x - xv[m][0] * s1z) * cB,
                  (xv[m][0] * s1y - xv[m][1] * s1x) * cB);

        // ---- emission (lane owns cols n=2qc, 2qc+1 of its 4 rows) ----
#pragma unroll
        for (int mt = 0; mt < 2; mt++)
#pragma unroll
            for (int h = 0; h < 2; h++) {
                int srcl = mt * 16 + h * 8 + r4;
                int dstr = __shfl_sync(FULLMASK, dst, srcl);
                if (IS_K) {
                    const float* ap = g_a + (size_t)dstr * 32;
                    float2 a01 = *(const float2*)(ap + 2 * qc);
                    float lp = a01.x * osA[mt][h][0] + a01.y * osA[mt][h][1];
                    float2 v0 = *(const float2*)(ap + 8 + 6 * qc);
                    float2 v1 = *(const float2*)(ap + 8 + 6 * qc + 2);
                    float2 v2 = *(const float2*)(ap + 8 + 6 * qc + 4);
                    lp += v0.x * ovA[mt][h][0][0] + v0.y * ovA[mt][h][0][1];
                    lp += v1.x * ovA[mt][h][0][2] + v1.y * ovA[mt][h][1][0];
                    lp += v2.x * ovA[mt][h][1][1] + v2.y * ovA[mt][h][1][2];
                    lp += __shfl_xor_sync(FULLMASK, lp, 1);
                    lp += __shfl_xor_sync(FULLMASK, lp, 2);
                    if (qc == 0) {
                        int er = tile * 256 + wid * 32 + srcl;
                        if (er < NE) {
                            float ex = __expf(lp);
                            g_exp[er] = ex;
                            red2(&g_zc[(size_t)dstr * 2], ex, 1.0f);
                        }
                    }
                } else {
                    float* ob = out + (size_t)dstr * 32;
                    red2(ob + 2 * qc, osA[mt][h][0], osA[mt][h][1]);
                    red2(ob + 8 + 6 * qc,     ovA[mt][h][0][0], ovA[mt][h][0][1]);
                    red2(ob + 8 + 6 * qc + 2, ovA[mt][h][0][2], ovA[mt][h][1][0]);
                    red2(ob + 8 + 6 * qc + 4, ovA[mt][h][1][1], ovA[mt][h][1][2]);
                }
            }
    }
}

extern "C" void kernel_launch(void* const* d_in, const int* in_sizes, int n_in,
                              void* d_out, int out_size) {
    const float* na    = (const float*)d_in[0];
    const int*   ei    = (const int*)d_in[1];
    const float* eattr = (const float*)d_in[2];
    const float* esh   = (const float*)d_in[3];
    const float* Wq0   = (const float*)d_in[4];
    const float* Wq1   = (const float*)d_in[5];
    const float* kW1   = (const float*)d_in[6];
    const float* kW2   = (const float*)d_in[7];
    const float* vW1   = (const float*)d_in[8];
    const float* vW2   = (const float*)d_in[9];
    const float* Wd0   = (const float*)d_in[10];
    const float* Wd1   = (const float*)d_in[11];
    float* out = (float*)d_out;

    cudaFuncSetAttribute(fused_pass<1>, cudaFuncAttributeMaxDynamicSharedMemorySize, SMEM_BYTES);
    cudaFuncSetAttribute(fused_pass<0>, cudaFuncAttributeMaxDynamicSharedMemorySize, SMEM_BYTES);

    zero_kernel<<<(NN * 32 + 255) / 256, 256>>>(out);
    node_prep<<<(NN + 127) / 128, 128>>>(na, Wq0, Wq1, Wd0, Wd1);
    fused_pass<1><<<296, 256, SMEM_BYTES>>>(na, ei, eattr, esh, kW1, kW2, out);
    fused_pass<0><<<296, 256, SMEM_BYTES>>>(na, ei, eattr, esh, vW1, vW2, out);
    finalize<<<(NN + 127) / 128, 128>>>(out);
}

// round 9
// speedup vs baseline: 6.6945x; 1.1963x over previous
#include <cuda_runtime.h>
#include <cuda_fp16.h>
#include <math.h>
#include <stdint.h>

#define NN 25000
#define NE 200000
#define NTILES ((NE + 255) / 256)
#define FULLMASK 0xffffffffu

// ---- scratch (no allocs allowed) ----
__device__ float g_a[NN * 32];    // per-node [a_s(8), a_v(8x3)]
__device__ float g_exp[NE];       // per-edge exp(logit)
__device__ float g_zc[NN * 2];    // interleaved [z, cnt]

#define INV_SQRT8  0.3535533905932738f
#define DOT_SC     0.5773502691896258f   // 1/sqrt(3)
#define CROSS_SC   0.7071067811865476f   // 1/sqrt(2)
#define OUTS_SC    0.25f                 // 1/sqrt(2*MUL)
#define OUTV_SC    0.2041241452319315f   // 1/sqrt(3*MUL)
#define LOGIT_VSC  0.5773502691896258f   // 1/sqrt(3)
#define LOGIT_SC   0.25f                 // 1/sqrt(2*MUL)

static __device__ __forceinline__ float fsilu(float x) {
    return __fdividef(x, 1.f + __expf(-x));
}
// h = silu(acc)*0.125  (acc already includes the 1/sqrt(16) folded into W1)
static __device__ __forceinline__ float hsilu(float x) {
    return fsilu(x) * 0.125f;
}

__device__ __forceinline__ uint32_t tf32r(float x) {
    uint32_t v;
    asm("cvt.rna.tf32.f32 %0, %1;" : "=r"(v) : "f"(x));
    return v;
}

__device__ __forceinline__ uint32_t pkh2(float a, float b) {
    __half2 h = __floats2half2_rn(a, b);   // lo = a (smaller k index)
    return *(uint32_t*)&h;
}

__device__ __forceinline__ void mma8(float* d, const uint32_t* a, const uint32_t* b) {
    asm volatile("mma.sync.aligned.m16n8k8.row.col.f32.tf32.tf32.f32 "
        "{%0,%1,%2,%3}, {%4,%5,%6,%7}, {%8,%9}, {%0,%1,%2,%3};"
        : "+f"(d[0]), "+f"(d[1]), "+f"(d[2]), "+f"(d[3])
        : "r"(a[0]), "r"(a[1]), "r"(a[2]), "r"(a[3]), "r"(b[0]), "r"(b[1]));
}

__device__ __forceinline__ void mma16(float* d, const uint32_t* a, uint32_t b0, uint32_t b1) {
    asm volatile("mma.sync.aligned.m16n8k16.row.col.f32.f16.f16.f32 "
        "{%0,%1,%2,%3}, {%4,%5,%6,%7}, {%8,%9}, {%0,%1,%2,%3};"
        : "+f"(d[0]), "+f"(d[1]), "+f"(d[2]), "+f"(d[3])
        : "r"(a[0]), "r"(a[1]), "r"(a[2]), "r"(a[3]), "r"(b0), "r"(b1));
}

__device__ __forceinline__ void red2(float* p, float a, float b) {
    asm volatile("red.global.add.v2.f32 [%0], {%1, %2};"
        :: "l"(p), "f"(a), "f"(b) : "memory");
}

// =====================  small kernels  =====================
__global__ void zero_kernel(float* __restrict__ out) {
    int i = blockIdx.x * blockDim.x + threadIdx.x;
    if (i < NN * 32) out[i] = 0.f;
    if (i < NN * 2) g_zc[i] = 0.f;
}

__global__ void node_prep(const float* __restrict__ na,
                          const float* __restrict__ Wq0, const float* __restrict__ Wq1,
                          const float* __restrict__ Wd0, const float* __restrict__ Wd1) {
    int i = blockIdx.x * blockDim.x + threadIdx.x;
    if (i >= NN) return;
    float ns[8], nv[8][3];
#pragma unroll
    for (int m = 0; m < 8; m++) ns[m] = na[i * 32 + m];
#pragma unroll
    for (int m = 0; m < 8; m++)
#pragma unroll
        for (int c = 0; c < 3; c++) nv[m][c] = na[i * 32 + 8 + m * 3 + c];
    float qs[8], qv[8][3];
#pragma unroll
    for (int k = 0; k < 8; k++) {
        float a = 0.f;
#pragma unroll
        for (int m = 0; m < 8; m++) a += ns[m] * Wq0[m * 8 + k];
        qs[k] = a * INV_SQRT8;
    }
#pragma unroll
    for (int k = 0; k < 8; k++)
#pragma unroll
        for (int c = 0; c < 3; c++) {
            float a = 0.f;
#pragma unroll
            for (int m = 0; m < 8; m++) a += nv[m][c] * Wq1[m * 8 + k];
            qv[k][c] = a * INV_SQRT8;
        }
#pragma unroll
    for (int n = 0; n < 8; n++) {
        float a = 0.f;
#pragma unroll
        for (int k = 0; k < 8; k++) a += Wd0[k * 8 + n] * qs[k];
        g_a[i * 32 + n] = a;
    }
#pragma unroll
    for (int n = 0; n < 8; n++)
#pragma unroll
        for (int c = 0; c < 3; c++) {
            float a = 0.f;
#pragma unroll
            for (int k = 0; k < 8; k++) a += Wd1[k * 8 + n] * qv[k][c];
            g_a[i * 32 + 8 + n * 3 + c] = a;
        }
}

__global__ void finalize(float* __restrict__ out) {
    int i = blockIdx.x * blockDim.x + threadIdx.x;
    if (i >= NN) return;
    float c = g_zc[i * 2 + 1];
    float z = g_zc[i * 2] / fmaxf(c, 1.0f);
    float s = (z > 0.f) ? rsqrtf(z) : 0.f;
#pragma unroll
    for (int t = 0; t < 32; t++) out[i * 32 + t] *= s;
}

// =====================  fused edge pass  =====================
// smem (f32 units): sW1u[16*72 tf32, pre-scaled 0.25] | sEAu[256*20 tf32] | sB[2560 uint4]
#define SEA_ST 20
#define SW1_SZ 1152
#define SEA_OFF SW1_SZ
#define SB_OFF (SW1_SZ + 256 * SEA_ST)
#define SMEM_FLOATS (SB_OFF + 10240)
#define SMEM_BYTES (SMEM_FLOATS * 4)

// layer-2 GEMM of one n-tile: dnt[2][4], K=64 (2 uint4 B loads)
#define GEMM_NT(P, NT, DNT) do {                                                 \
    _Pragma("unroll")                                                            \
    for (int q_ = 0; q_ < 4; q_++) { DNT[0][q_] = 0.f; DNT[1][q_] = 0.f; }       \
    _Pragma("unroll")                                                            \
    for (int kkp_ = 0; kkp_ < 2; kkp_++) {                                       \
        uint4 bv_ = sBf4[(((P) * 8 + (NT)) * 2 + kkp_) * 32 + lane];             \
        mma16(DNT[0], &aF[kkp_ * 2][0], bv_.x, bv_.y);                           \
        mma16(DNT[1], &aF[kkp_ * 2][4], bv_.x, bv_.y);                           \
        mma16(DNT[0], &aF[kkp_ * 2 + 1][0], bv_.z, bv_.w);                       \
        mma16(DNT[1], &aF[kkp_ * 2 + 1][4], bv_.z, bv_.w);                       \
    } } while (0)

// scalar path: T[mt][h][pair] += dnt * f(m) shuffled from the row-owner lane
#define PATH_S(P, FEXPR, T) do {                                                 \
    _Pragma("unroll")                                                            \
    for (int nt_ = 0; nt_ < 8; nt_++) {                                          \
        float dnt[2][4];                                                         \
        GEMM_NT(P, nt_, dnt);                                                    \
        { int m = nt_; float fv_ = (FEXPR);                                      \
          float f00_ = __shfl_sync(FULLMASK, fv_, r4);                           \
          float f01_ = __shfl_sync(FULLMASK, fv_, 8 + r4);                       \
          float f10_ = __shfl_sync(FULLMASK, fv_, 16 + r4);                      \
          float f11_ = __shfl_sync(FULLMASK, fv_, 24 + r4);                      \
          T[0][0][0] += dnt[0][0] * f00_; T[0][0][1] += dnt[0][1] * f00_;        \
          T[0][1][0] += dnt[0][2] * f01_; T[0][1][1] += dnt[0][3] * f01_;        \
          T[1][0][0] += dnt[1][0] * f10_; T[1][0][1] += dnt[1][1] * f10_;        \
          T[1][1][0] += dnt[1][2] * f11_; T[1][1][1] += dnt[1][3] * f11_; }      \
    } } while (0)

// vector path: ovA[mt][h][pair][c] += dnt * f_c(m)
#define PATH_V(P, FX, FY, FZ) do {                                               \
    _Pragma("unroll")                                                            \
    for (int nt_ = 0; nt_ < 8; nt_++) {                                          \
        float dnt[2][4];                                                         \
        GEMM_NT(P, nt_, dnt);                                                    \
        { int m = nt_;                                                           \
          float fx_ = (FX), fy_ = (FY), fz_ = (FZ);                              \
          float gx00_ = __shfl_sync(FULLMASK, fx_, r4);                          \
          float gx01_ = __shfl_sync(FULLMASK, fx_, 8 + r4);                      \
          float gx10_ = __shfl_sync(FULLMASK, fx_, 16 + r4);                     \
          float gx11_ = __shfl_sync(FULLMASK, fx_, 24 + r4);                     \
          float gy00_ = __shfl_sync(FULLMASK, fy_, r4);                          \
          float gy01_ = __shfl_sync(FULLMASK, fy_, 8 + r4);                      \
          float gy10_ = __shfl_sync(FULLMASK, fy_, 16 + r4);                     \
          float gy11_ = __shfl_sync(FULLMASK, fy_, 24 + r4);                     \
          float gz00_ = __shfl_sync(FULLMASK, fz_, r4);                          \
          float gz01_ = __shfl_sync(FULLMASK, fz_, 8 + r4);                      \
          float gz10_ = __shfl_sync(FULLMASK, fz_, 16 + r4);                     \
          float gz11_ = __shfl_sync(FULLMASK, fz_, 24 + r4);                     \
          ovA[0][0][0][0] += dnt[0][0] * gx00_; ovA[0][0][1][0] += dnt[0][1] * gx00_; \
          ovA[0][1][0][0] += dnt[0][2] * gx01_; ovA[0][1][1][0] += dnt[0][3] * gx01_; \
          ovA[1][0][0][0] += dnt[1][0] * gx10_; ovA[1][0][1][0] += dnt[1][1] * gx10_; \
          ovA[1][1][0][0] += dnt[1][2] * gx11_; ovA[1][1][1][0] += dnt[1][3] * gx11_; \
          ovA[0][0][0][1] += dnt[0][0] * gy00_; ovA[0][0][1][1] += dnt[0][1] * gy00_; \
          ovA[0][1][0][1] += dnt[0][2] * gy01_; ovA[0][1][1][1] += dnt[0][3] * gy01_; \
          ovA[1][0][0][1] += dnt[1][0] * gy10_; ovA[1][0][1][1] += dnt[1][1] * gy10_; \
          ovA[1][1][0][1] += dnt[1][2] * gy11_; ovA[1][1][1][1] += dnt[1][3] * gy11_; \
          ovA[0][0][0][2] += dnt[0][0] * gz00_; ovA[0][0][1][2] += dnt[0][1] * gz00_; \
          ovA[0][1][0][2] += dnt[0][2] * gz01_; ovA[0][1][1][2] += dnt[0][3] * gz01_; \
          ovA[1][0][0][2] += dnt[1][0] * gz10_; ovA[1][0][1][2] += dnt[1][1] * gz10_; \
          ovA[1][1][0][2] += dnt[1][2] * gz11_; ovA[1][1][1][2] += dnt[1][3] * gz11_; } \
    } } while (0)

template <int IS_K>
__global__ void __launch_bounds__(256, 2) fused_pass(
    const float* __restrict__ na, const int* __restrict__ ei,
    const float* __restrict__ eattr, const float* __restrict__ esh,
    const float* __restrict__ W1, const float* __restrict__ W2,
    float* __restrict__ out) {
    extern __shared__ float sm[];
    uint32_t* sW1u = (uint32_t*)sm;
    uint32_t* sEAu = (uint32_t*)(sm + SEA_OFF);
    const uint4* sBf4 = (const uint4*)(sm + SB_OFF);

    const int tid = threadIdx.x;
    const int wid = tid >> 5;
    const int lane = tid & 31;
    const int r4 = lane >> 2;
    const int qc = lane & 3;

    // stage W1 (tf32, pre-scaled by 1/sqrt(16), stride 72 -> conflict-free b-frags)
    for (int idx = tid; idx < 1024; idx += 256) {
        int i = idx >> 6, j = idx & 63;
        sW1u[i * 72 + j] = tf32r(W1[idx] * 0.25f);
    }
    // stage W2 as fp16 mma B-fragments
    {
        uint4* wB = (uint4*)(sm + SB_OFF);
        for (int idx = tid; idx < 2560; idx += 256) {
            int lane_ = idx & 31;
            int kkp = (idx >> 5) & 1;
            int nt = (idx >> 6) & 7;
            int p = idx >> 9;
            int col = p * 64 + nt * 8 + (lane_ >> 2);
            int k0 = (kkp * 2) * 16 + 2 * (lane_ & 3);
            int k1 = k0 + 16;
            uint4 v;
            v.x = pkh2(W2[k0 * 320 + col],       W2[(k0 + 1) * 320 + col]);
            v.y = pkh2(W2[(k0 + 8) * 320 + col], W2[(k0 + 9) * 320 + col]);
            v.z = pkh2(W2[k1 * 320 + col],       W2[(k1 + 1) * 320 + col]);
            v.w = pkh2(W2[(k1 + 8) * 320 + col], W2[(k1 + 9) * 320 + col]);
            wB[idx] = v;
        }
    }
    __syncthreads();

    for (int tile = blockIdx.x; tile < NTILES; tile += gridDim.x) {
        const int e = tile * 256 + tid;
        const bool valid = (e < NE);

        // ---- stage this edge's attr (tf32) into sEA ----
        float ea[16];
        if (valid) {
            const float4* p = (const float4*)(eattr + (size_t)e * 16);
#pragma unroll
            for (int q = 0; q < 4; q++) {
                float4 v = p[q];
                ea[q * 4 + 0] = v.x; ea[q * 4 + 1] = v.y;
                ea[q * 4 + 2] = v.z; ea[q * 4 + 3] = v.w;
            }
        } else {
#pragma unroll
            for (int q = 0; q < 16; q++) ea[q] = 0.f;
        }
        __syncthreads();   // prior tile's sEA readers done
#pragma unroll
        for (int q = 0; q < 4; q++) {
            uint4 v;
            v.x = tf32r(ea[q * 4 + 0]); v.y = tf32r(ea[q * 4 + 1]);
            v.z = tf32r(ea[q * 4 + 2]); v.w = tf32r(ea[q * 4 + 3]);
            *(uint4*)(sEAu + tid * SEA_ST + q * 4) = v;
        }
        __syncthreads();

        // ---- layer-1 GEMM (tf32): D1[mt][nt] = EA(32x16) @ W1s(16x64) ----
        float D1[2][8][4];
#pragma unroll
        for (int mt = 0; mt < 2; mt++)
#pragma unroll
            for (int nt = 0; nt < 8; nt++)
#pragma unroll
                for (int q = 0; q < 4; q++) D1[mt][nt][q] = 0.f;
        {
            uint32_t a1f[2][2][4];
#pragma unroll
            for (int mt = 0; mt < 2; mt++)
#pragma unroll
                for (int kk = 0; kk < 2; kk++) {
                    int row = wid * 32 + mt * 16;
                    a1f[mt][kk][0] = sEAu[(row + r4) * SEA_ST + 8 * kk + qc];
                    a1f[mt][kk][1] = sEAu[(row + 8 + r4) * SEA_ST + 8 * kk + qc];
                    a1f[mt][kk][2] = sEAu[(row + r4) * SEA_ST + 8 * kk + 4 + qc];
                    a1f[mt][kk][3] = sEAu[(row + 8 + r4) * SEA_ST + 8 * kk + 4 + qc];
                }
#pragma unroll
            for (int nt = 0; nt < 8; nt++)
#pragma unroll
                for (int kk = 0; kk < 2; kk++) {
                    uint32_t b[2];
                    b[0] = sW1u[(8 * kk + qc) * 72 + 8 * nt + r4];
                    b[1] = sW1u[(8 * kk + 4 + qc) * 72 + 8 * nt + r4];
                    mma8(D1[0][nt], a1f[0][kk], b);
                    mma8(D1[1][nt], a1f[1][kk], b);
                }
        }
        // silu + pack -> layer-2 A fragments (fragment layouts coincide)
        uint32_t aF[4][8];
#pragma unroll
        for (int mt = 0; mt < 2; mt++)
#pragma unroll
            for (int nt = 0; nt < 8; nt++)
#pragma unroll
                for (int q = 0; q < 4; q++) D1[mt][nt][q] = hsilu(D1[mt][nt][q]);
#pragma unroll
        for (int kk = 0; kk < 4; kk++)
#pragma unroll
            for (int mt = 0; mt < 2; mt++) {
                aF[kk][mt * 4 + 0] = pkh2(D1[mt][2 * kk][0],     D1[mt][2 * kk][1]);
                aF[kk][mt * 4 + 1] = pkh2(D1[mt][2 * kk][2],     D1[mt][2 * kk][3]);
                aF[kk][mt * 4 + 2] = pkh2(D1[mt][2 * kk + 1][0], D1[mt][2 * kk + 1][1]);
                aF[kk][mt * 4 + 3] = pkh2(D1[mt][2 * kk + 1][2], D1[mt][2 * kk + 1][3]);
            }

        // ---- per-edge features (owner = this thread's edge) ----
        int dst = 0;
        float xs[8], xv[8][3];
        float s0 = 0.f, s1x = 0.f, s1y = 0.f, s1z = 0.f;
        float m0 = 0.f, m1 = 0.f;
        if (valid) {
            int srcn = ei[e];
            dst = ei[NE + e];
            const float4* xp = (const float4*)(na + (size_t)srcn * 32);
#pragma unroll
            for (int q = 0; q < 2; q++) {
                float4 v = xp[q];
                xs[q * 4 + 0] = v.x; xs[q * 4 + 1] = v.y;
                xs[q * 4 + 2] = v.z; xs[q * 4 + 3] = v.w;
            }
#pragma unroll
            for (int q = 0; q < 6; q++) {
                float4 v = xp[2 + q];
                ((float*)xv)[q * 4 + 0] = v.x; ((float*)xv)[q * 4 + 1] = v.y;
                ((float*)xv)[q * 4 + 2] = v.z; ((float*)xv)[q * 4 + 3] = v.w;
            }
            float4 sh = *(const float4*)(esh + (size_t)e * 4);
            s0 = sh.x; s1x = sh.y; s1y = sh.z; s1z = sh.w;
            if (IS_K) {
                m0 = OUTS_SC * LOGIT_SC;
                m1 = OUTV_SC * LOGIT_VSC * LOGIT_SC;
            } else {
                float att = sqrtf(g_exp[e]);
                m0 = att * OUTS_SC;
                m1 = att * OUTV_SC;
            }
        } else {
#pragma unroll
            for (int m = 0; m < 8; m++) {
                xs[m] = 0.f; xv[m][0] = xv[m][1] = xv[m][2] = 0.f;
            }
        }
        const float s0A = s0 * m0;           // path0
        const float dA  = DOT_SC * m0;       // path3
        const float s0B = s0 * m1;           // path2
        const float cB  = CROSS_SC * m1;     // path4

        float osA[2][2][2];
        float ovA[2][2][2][3];
#pragma unroll
        for (int a = 0; a < 2; a++)
#pragma unroll
            for (int b = 0; b < 2; b++) {
                osA[a][b][0] = osA[a][b][1] = 0.f;
#pragma unroll
                for (int p = 0; p < 2; p++)
                    ovA[a][b][p][0] = ovA[a][b][p][1] = ovA[a][b][p][2] = 0.f;
            }

        // path 0: os += w0 @ (xs*s0)
        PATH_S(0, xs[m] * s0A, osA);

        // path 1: ov += (w1 @ xs) outer s1
        {
            float t8a[2][2][2];
#pragma unroll
            for (int a = 0; a < 2; a++)
#pragma unroll
                for (int b = 0; b < 2; b++) t8a[a][b][0] = t8a[a][b][1] = 0.f;
            PATH_S(1, xs[m] * m1, t8a);
#pragma unroll
            for (int mt = 0; mt < 2; mt++)
#pragma unroll
                for (int h = 0; h < 2; h++) {
                    int srcl = mt * 16 + h * 8 + r4;
                    float sx = __shfl_sync(FULLMASK, s1x, srcl);
                    float sy = __shfl_sync(FULLMASK, s1y, srcl);
                    float sz = __shfl_sync(FULLMASK, s1z, srcl);
                    ovA[mt][h][0][0] += t8a[mt][h][0] * sx;
                    ovA[mt][h][1][0] += t8a[mt][h][1] * sx;
                    ovA[mt][h][0][1] += t8a[mt][h][0] * sy;
                    ovA[mt][h][1][1] += t8a[mt][h][1] * sy;
                    ovA[mt][h][0][2] += t8a[mt][h][0] * sz;
                    ovA[mt][h][1][2] += t8a[mt][h][1] * sz;
                }
        }

        // path 2: ov += (w2 @ xv) * s0
        PATH_V(2, xv[m][0] * s0B, xv[m][1] * s0B, xv[m][2] * s0B);

        // path 3: os += w3 @ ((xv.s1)/sqrt3)
        PATH_S(3, (xv[m][0] * s1x + xv[m][1] * s1y + xv[m][2] * s1z) * dA, osA);

        // path 4: ov += w4 @ (cross(xv, s1)/sqrt2)
        PATH_V(4, (xv[m][1] * s1z - xv[m][2] * s1y) * cB,
                  (xv[m][2] * s1x - xv[m][0] * s1z) * cB,
                  (xv[m][0] * s1y - xv[m][1] * s1x) * cB);

        // ---- emission (lane owns cols n=2qc, 2qc+1 of its 4 rows) ----
#pragma unroll
        for (int mt = 0; mt < 2; mt++)
#pragma unroll
            for (int h = 0; h < 2; h++) {
                int srcl = mt * 16 + h * 8 + r4;
                int dstr = __shfl_sync(FULLMASK, dst, srcl);
                if (IS_K) {
                    const float* ap = g_a + (size_t)dstr * 32;
                    float2 a01 = *(const float2*)(ap + 2 * qc);
                    float lp = a01.x * osA[mt][h][0] + a01.y * osA[mt][h][1];
                    float2 v0 = *(const float2*)(ap + 8 + 6 * qc);
                    float2 v1 = *(const float2*)(ap + 8 + 6 * qc + 2);
                    float2 v2 = *(const float2*)(ap + 8 + 6 * qc + 4);
                    lp += v0.x * ovA[mt][h][0][0] + v0.y * ovA[mt][h][0][1];
                    lp += v1.x * ovA[mt][h][0][2] + v1.y * ovA[mt][h][1][0];
                    lp += v2.x * ovA[mt][h][1][1] + v2.y * ovA[mt][h][1][2];
                    lp += __shfl_xor_sync(FULLMASK, lp, 1);
                    lp += __shfl_xor_sync(FULLMASK, lp, 2);
                    if (qc == 0) {
                        int er = tile * 256 + wid * 32 + srcl;
                        if (er < NE) {
                            float ex = __expf(lp);
                            g_exp[er] = ex;
                            red2(&g_zc[(size_t)dstr * 2], ex, 1.0f);
                        }
                    }
                } else {
                    float* ob = out + (size_t)dstr * 32;
                    red2(ob + 2 * qc, osA[mt][h][0], osA[mt][h][1]);
                    red2(ob + 8 + 6 * qc,     ovA[mt][h][0][0], ovA[mt][h][0][1]);
                    red2(ob + 8 + 6 * qc + 2, ovA[mt][h][0][2], ovA[mt][h][1][0]);
                    red2(ob + 8 + 6 * qc + 4, ovA[mt][h][1][1], ovA[mt][h][1][2]);
                }
            }
    }
}

extern "C" void kernel_launch(void* const* d_in, const int* in_sizes, int n_in,
                              void* d_out, int out_size) {
    const float* na    = (const float*)d_in[0];
    const int*   ei    = (const int*)d_in[1];
    const float* eattr = (const float*)d_in[2];
    const float* esh   = (const float*)d_in[3];
    const float* Wq0   = (const float*)d_in[4];
    const float* Wq1   = (const float*)d_in[5];
    const float* kW1   = (const float*)d_in[6];
    const float* kW2   = (const float*)d_in[7];
    const float* vW1   = (const float*)d_in[8];
    const float* vW2   = (const float*)d_in[9];
    const float* Wd0   = (const float*)d_in[10];
    const float* Wd1   = (const float*)d_in[11];
    float* out = (float*)d_out;

    cudaFuncSetAttribute(fused_pass<1>, cudaFuncAttributeMaxDynamicSharedMemorySize, SMEM_BYTES);
    cudaFuncSetAttribute(fused_pass<0>, cudaFuncAttributeMaxDynamicSharedMemorySize, SMEM_BYTES);

    zero_kernel<<<(NN * 32 + 255) / 256, 256>>>(out);
    node_prep<<<(NN + 127) / 128, 128>>>(na, Wq0, Wq1, Wd0, Wd1);
    fused_pass<1><<<296, 256, SMEM_BYTES>>>(na, ei, eattr, esh, kW1, kW2, out);
    fused_pass<0><<<296, 256, SMEM_BYTES>>>(na, ei, eattr, esh, vW1, vW2, out);
    finalize<<<(NN + 127) / 128, 128>>>(out);
}